// round 8
// baseline (speedup 1.0000x reference)
#include <cuda_runtime.h>
#include <cuda_fp16.h>
#include <math.h>
#include <stdint.h>

#define DIMN 2048
#define BATCH 4
#define LQ    4096
#define KC    576
#define KT    4672          // KC + LQ
#define KTP   4864          // padded N for the S GEMM (19*256)

typedef __half h16;

// ---------------------------------------------------------------------------
// Scratch (__device__ globals — zero-initialized; K rows [KT,KTP) stay 0)
// fp16 2-pass scheme: A operands stored hi-only, B operands hi+lo.
// ---------------------------------------------------------------------------
__device__ h16 g_ch [(size_t)BATCH*LQ*DIMN];   // chunk hi
__device__ h16 g_cl [(size_t)BATCH*LQ*DIMN];   // chunk lo
__device__ h16 g_wqh[(size_t)DIMN*DIMN], g_wql[(size_t)DIMN*DIMN];
__device__ h16 g_wkh[(size_t)DIMN*DIMN], g_wkl[(size_t)DIMN*DIMN];
__device__ h16 g_wvh[(size_t)DIMN*DIMN];
__device__ h16 g_woh[(size_t)DIMN*DIMN], g_wol[(size_t)DIMN*DIMN];
__device__ h16 g_qh [(size_t)BATCH*LQ*DIMN];
__device__ h16 g_kh [(size_t)BATCH*KTP*DIMN], g_kl[(size_t)BATCH*KTP*DIMN];
__device__ h16 g_vh [(size_t)BATCH*DIMN*KT],  g_vl[(size_t)BATCH*DIMN*KT]; // V^T [b][d][kt]
__device__ float g_s [(size_t)BATCH*LQ*KTP];
__device__ h16 g_ph [(size_t)BATCH*LQ*KT];
__device__ h16 g_ah [(size_t)BATCH*LQ*DIMN];

// ---------------------------------------------------------------------------
// helpers
// ---------------------------------------------------------------------------
__device__ __forceinline__ uint32_t s2u(const void* p) {
    uint32_t a;
    asm("{ .reg .u64 t; cvta.to.shared.u64 t, %1; cvt.u32.u64 %0, t; }" : "=r"(a) : "l"(p));
    return a;
}
__device__ __forceinline__ void cpa16(uint32_t d, const void* s) {
    asm volatile("cp.async.cg.shared.global [%0], [%1], 16;" :: "r"(d), "l"(s));
}
#define CP_COMMIT() asm volatile("cp.async.commit_group;" ::: "memory")
#define CP_WAIT1()  asm volatile("cp.async.wait_group 1;" ::: "memory")
#define CP_WAIT0()  asm volatile("cp.async.wait_group 0;" ::: "memory")

#define LDSM4(r, a) \
    asm volatile("ldmatrix.sync.aligned.m8n8.x4.shared.b16 {%0,%1,%2,%3}, [%4];" \
                 : "=r"((r)[0]), "=r"((r)[1]), "=r"((r)[2]), "=r"((r)[3]) : "r"(a))

__device__ __forceinline__ void mma16816(float* d, const uint32_t* a,
                                         uint32_t b0, uint32_t b1) {
    asm volatile(
        "mma.sync.aligned.m16n8k16.row.col.f32.f16.f16.f32 "
        "{%0,%1,%2,%3}, {%4,%5,%6,%7}, {%8,%9}, {%0,%1,%2,%3};"
        : "+f"(d[0]), "+f"(d[1]), "+f"(d[2]), "+f"(d[3])
        : "r"(a[0]), "r"(a[1]), "r"(a[2]), "r"(a[3]), "r"(b0), "r"(b1));
}

// x = hi(fp16) + lo(fp16); residual ~2^-22 |x|
__device__ __forceinline__ void split2h(float x0, float x1, uint32_t& h, uint32_t& l) {
    __half2 hp = __floats2half2_rn(x0, x1);
    float2 hf = __half22float2(hp);
    __half2 lp = __floats2half2_rn(x0 - hf.x, x1 - hf.y);
    h = *reinterpret_cast<uint32_t*>(&hp);
    l = *reinterpret_cast<uint32_t*>(&lp);
}
__device__ __forceinline__ uint32_t round2h(float x0, float x1) {
    __half2 hp = __floats2half2_rn(x0, x1);
    return *reinterpret_cast<uint32_t*>(&hp);
}

// ---------------------------------------------------------------------------
// fp16 2-pass mma.sync GEMM: C tile 128x256, BK=32, 2-stage cp.async pipeline.
// C = Ah·Bh^T + Ah·Bl^T. A[M,K] hi-only, B[N,K] hi+lo, row-major (NT). fp32 acc.
// 8 warps in 2(M) x 4(N); warp tile 64x64 (128 accum regs/thread, 1 CTA/SM).
// OUTM: 0 fp32 out, 1 fp16 hi-only out, 2 fp16 hi+lo out.
// BIASM: 0 none, 1 bias[col], 2 bias[row]
// TRI:  0 none, 1 = skip block if col0 >= KC+row0+BMT (S GEMM),
//       2 = clamp K loop to KC+row0+BMT (AV GEMM; heavy rows scheduled first)
// ---------------------------------------------------------------------------
#define BMT 128
#define BNT 256
#define BKT 32
#define APAD 40                            // fp16 row stride (32+8) -> 80B
#define A_TILE (128 * APAD * 2)            // 10240 bytes
#define B_TILE (256 * APAD * 2)            // 20480 bytes
#define STAGE_B (A_TILE + 2 * B_TILE)      // 51200
#define SMEM_MMA (2 * STAGE_B)             // 102400 bytes

template<int OUTM, int BIASM, int TRI>
__global__ __launch_bounds__(256)
void gemm_mma(const h16* __restrict__ Ah,
              const h16* __restrict__ Bh, const h16* __restrict__ Bl,
              const float* __restrict__ bias,
              float* __restrict__ Cf, h16* __restrict__ Ch, h16* __restrict__ Cl,
              int K, int lda, int ldb, int ldc,
              long long sA, long long sB, long long sC)
{
    // TRI==2: reverse row order so the heaviest (longest-K) CTAs start first
    const int row0 = (TRI == 2 ? (int)(gridDim.y - 1 - blockIdx.y) : (int)blockIdx.y) * BMT;
    const int col0 = blockIdx.x * BNT;
    if (TRI == 1 && col0 >= KC + row0 + BMT) return;   // fully-masked S tile

    extern __shared__ h16 sm[];
    const uint32_t smb = s2u(sm);
    const int tid  = threadIdx.x;
    const int lane = tid & 31, warp = tid >> 5;
    const int wm = warp & 1, wn = warp >> 1;    // warp grid 2 (M) x 4 (N)
    const size_t zA = (size_t)blockIdx.z * sA;
    const size_t zB = (size_t)blockIdx.z * sB;
    const size_t zC = (size_t)blockIdx.z * sC;

    int kchunks = K / BKT;
    if (TRI == 2) {
        int lim = (KC + row0 + BMT) / BKT;      // multiple of 32 by construction
        if (lim < kchunks) kchunks = lim;
    }

    // cp.async mapping: A rows (tid>>2), +64; B rows (tid>>2)+64j, j=0..3
    const int lrow = tid >> 2;
    const int lcol = (tid & 3) * 8;
    const uint32_t oa1 = (lrow * APAD + lcol) * 2;
    const uint32_t oa2 = ((lrow + 64) * APAD + lcol) * 2;

    auto issue = [&](int kc, int st) {
        const size_t ao = zA + (size_t)(row0 + lrow) * lda + (size_t)kc * BKT + lcol;
        const size_t bo = zB + (size_t)(col0 + lrow) * ldb + (size_t)kc * BKT + lcol;
        const uint32_t base = smb + st * STAGE_B;
        cpa16(base + oa1, Ah + ao);
        cpa16(base + oa2, Ah + ao + (size_t)64 * lda);
        const uint32_t bhb = base + A_TILE;
        const uint32_t blb = base + A_TILE + B_TILE;
#pragma unroll
        for (int j = 0; j < 4; j++) {
            const uint32_t ob = ((lrow + 64 * j) * APAD + lcol) * 2;
            cpa16(bhb + ob, Bh + bo + (size_t)(64 * j) * ldb);
            cpa16(blb + ob, Bl + bo + (size_t)(64 * j) * ldb);
        }
    };

    float acc[4][8][4];
#pragma unroll
    for (int i = 0; i < 4; i++)
#pragma unroll
        for (int j = 0; j < 8; j++)
#pragma unroll
            for (int e = 0; e < 4; e++) acc[i][j][e] = 0.f;

    // ldmatrix per-thread address components
    const int am = wm * 64 + (lane & 15);
    const int ak = (lane >> 4) * 8;
    const int bn = wn * 64 + (lane & 15);

    issue(0, 0); CP_COMMIT();

    for (int kc = 0; kc < kchunks; ++kc) {
        const int st = kc & 1;
        if (kc + 1 < kchunks) { issue(kc + 1, (kc + 1) & 1); CP_COMMIT(); CP_WAIT1(); }
        else                  { CP_WAIT0(); }
        __syncthreads();

        const uint32_t ah_ = smb + st * STAGE_B;
        const uint32_t bh_ = ah_ + A_TILE;
        const uint32_t bl_ = ah_ + A_TILE + B_TILE;
#pragma unroll
        for (int ks = 0; ks < 2; ks++) {
            uint32_t af[4][4], bh[4][4], bl[4][4];
            // load A(hi) + B(hi), run the hh group
#pragma unroll
            for (int mt = 0; mt < 4; mt++)
                LDSM4(af[mt], ah_ + (((am + mt * 16) * APAD) + ks * 16 + ak) * 2);
#pragma unroll
            for (int pr = 0; pr < 4; pr++)
                LDSM4(bh[pr], bh_ + (((bn + pr * 16) * APAD) + ks * 16 + ak) * 2);
#pragma unroll
            for (int mt = 0; mt < 4; mt++)
#pragma unroll
                for (int nt = 0; nt < 8; nt++)
                    mma16816(acc[mt][nt], af[mt],
                             bh[nt >> 1][nt & 1], bh[nt >> 1][(nt & 1) + 2]);
            // load B(lo) while hh drains, then hl group
#pragma unroll
            for (int pr = 0; pr < 4; pr++)
                LDSM4(bl[pr], bl_ + (((bn + pr * 16) * APAD) + ks * 16 + ak) * 2);
#pragma unroll
            for (int mt = 0; mt < 4; mt++)
#pragma unroll
                for (int nt = 0; nt < 8; nt++)
                    mma16816(acc[mt][nt], af[mt],
                             bl[nt >> 1][nt & 1], bl[nt >> 1][(nt & 1) + 2]);
        }
        __syncthreads();   // stage consumed before it is refilled
    }

    // epilogue
    const int crow = lane >> 2;
    const int ccol = (lane & 3) * 2;
#pragma unroll
    for (int mt = 0; mt < 4; mt++) {
        const size_t r0g = (size_t)row0 + wm * 64 + mt * 16 + crow;
#pragma unroll
        for (int nt = 0; nt < 8; nt++) {
            const int cg = col0 + wn * 64 + nt * 8 + ccol;
            float v0 = acc[mt][nt][0], v1 = acc[mt][nt][1];
            float v2 = acc[mt][nt][2], v3 = acc[mt][nt][3];
            if (BIASM == 1) {
                const float b0 = bias[cg], b1 = bias[cg + 1];
                v0 += b0; v1 += b1; v2 += b0; v3 += b1;
            }
            if (BIASM == 2) {
                const float b0 = bias[r0g], b1 = bias[r0g + 8];
                v0 += b0; v1 += b0; v2 += b1; v3 += b1;
            }
            if (OUTM == 0) {
                *reinterpret_cast<float2*>(&Cf[zC + r0g * ldc + cg])       = make_float2(v0, v1);
                *reinterpret_cast<float2*>(&Cf[zC + (r0g + 8) * ldc + cg]) = make_float2(v2, v3);
            } else if (OUTM == 1) {
                *reinterpret_cast<uint32_t*>(&Ch[zC + r0g * ldc + cg])       = round2h(v0, v1);
                *reinterpret_cast<uint32_t*>(&Ch[zC + (r0g + 8) * ldc + cg]) = round2h(v2, v3);
            } else {
                uint32_t h, l;
                split2h(v0, v1, h, l);
                *reinterpret_cast<uint32_t*>(&Ch[zC + r0g * ldc + cg]) = h;
                *reinterpret_cast<uint32_t*>(&Cl[zC + r0g * ldc + cg]) = l;
                split2h(v2, v3, h, l);
                *reinterpret_cast<uint32_t*>(&Ch[zC + (r0g + 8) * ldc + cg]) = h;
                *reinterpret_cast<uint32_t*>(&Cl[zC + (r0g + 8) * ldc + cg]) = l;
            }
        }
    }
}

// ---------------------------------------------------------------------------
// Elementwise fp32 -> split fp16 (hi+lo) and fp32 -> fp16 (hi only)
// ---------------------------------------------------------------------------
__global__ void split_kernel(const float* __restrict__ src, h16* __restrict__ h,
                             h16* __restrict__ l, size_t n4)
{
    size_t i = (size_t)blockIdx.x * blockDim.x + threadIdx.x;
    if (i >= n4) return;
    float4 v = reinterpret_cast<const float4*>(src)[i];
    uint32_t h0, h1, l0, l1;
    split2h(v.x, v.y, h0, l0);
    split2h(v.z, v.w, h1, l1);
    reinterpret_cast<uint2*>(h)[i] = make_uint2(h0, h1);
    reinterpret_cast<uint2*>(l)[i] = make_uint2(l0, l1);
}

__global__ void round_kernel(const float* __restrict__ src, h16* __restrict__ h, size_t n4)
{
    size_t i = (size_t)blockIdx.x * blockDim.x + threadIdx.x;
    if (i >= n4) return;
    float4 v = reinterpret_cast<const float4*>(src)[i];
    reinterpret_cast<uint2*>(h)[i] = make_uint2(round2h(v.x, v.y), round2h(v.z, v.w));
}

__global__ void cachek_kernel(const float* __restrict__ ck)
{
    const size_t per = (size_t)KC * DIMN / 4;
    size_t i = (size_t)blockIdx.x * blockDim.x + threadIdx.x;
    if (i >= BATCH * per) return;
    size_t b = i / per, r = i - b * per;
    float4 v = reinterpret_cast<const float4*>(ck)[i];
    uint32_t h0, h1, l0, l1;
    split2h(v.x, v.y, h0, l0);
    split2h(v.z, v.w, h1, l1);
    size_t dst = b * ((size_t)KTP * DIMN / 4) + r;
    reinterpret_cast<uint2*>(g_kh)[dst] = make_uint2(h0, h1);
    reinterpret_cast<uint2*>(g_kl)[dst] = make_uint2(l0, l1);
}

// cached_v [B,KC,D] -> transposed split into g_vh/g_vl [B,D,KT] cols [0,KC)
__global__ void cachev_kernel(const float* __restrict__ cv)
{
    __shared__ float t[32][33];
    const int b = blockIdx.z;
    const int r0 = blockIdx.x * 32;   // kc
    const int c0 = blockIdx.y * 32;   // d
    const int tx = threadIdx.x, ty0 = threadIdx.y;
#pragma unroll
    for (int s = 0; s < 4; s++) {
        int ty = ty0 + s * 8;
        t[ty][tx] = cv[((size_t)b * KC + r0 + ty) * DIMN + c0 + tx];
    }
    __syncthreads();
#pragma unroll
    for (int s = 0; s < 4; s++) {
        int ty = ty0 + s * 8;
        float x = t[tx][ty];
        __half h = __float2half_rn(x);
        __half lo = __float2half_rn(x - __half2float(h));
        size_t o = ((size_t)b * DIMN + c0 + ty) * KT + r0 + tx;
        g_vh[o] = h;
        g_vl[o] = lo;
    }
}

// ---------------------------------------------------------------------------
// Masked softmax: row q sees [0, KC+q+1); emits fp16 weights (0 beyond).
// ---------------------------------------------------------------------------
__global__ void softmax_kernel(const float* __restrict__ S, h16* __restrict__ Wh,
                               float scale)
{
    __shared__ float sbuf[KT];
    __shared__ float red[256];
    const int q = blockIdx.x, b = blockIdx.y;
    const float* row = S + ((size_t)b * LQ + q) * KTP;
    h16* wh = Wh + ((size_t)b * LQ + q) * KT;
    const int valid = KC + q + 1;
    const int tid = threadIdx.x;

    float m = -1e30f;
    for (int c = tid; c < valid; c += 256) m = fmaxf(m, row[c] * scale);
    red[tid] = m; __syncthreads();
    for (int s = 128; s > 0; s >>= 1) { if (tid < s) red[tid] = fmaxf(red[tid], red[tid + s]); __syncthreads(); }
    m = red[0]; __syncthreads();

    float sum = 0.f;
    for (int c = tid; c < valid; c += 256) {
        float e = __expf(row[c] * scale - m);
        sbuf[c] = e;
        sum += e;
    }
    red[tid] = sum; __syncthreads();
    for (int s = 128; s > 0; s >>= 1) { if (tid < s) red[tid] += red[tid + s]; __syncthreads(); }
    const float inv = 1.f / red[0];
    __syncthreads();

    for (int c = tid; c < KT; c += 256)
        wh[c] = __float2half_rn((c < valid) ? sbuf[c] * inv : 0.f);
}

// ---------------------------------------------------------------------------
// kernel_launch
// ---------------------------------------------------------------------------
extern "C" void kernel_launch(void* const* d_in, const int* in_sizes, int n_in,
                              void* d_out, int out_size)
{
    const float* chunk    = (const float*)d_in[0];
    const float* cached_k = (const float*)d_in[1];
    const float* cached_v = (const float*)d_in[2];
    int wi = 3;
    while (wi < n_in && in_sizes[wi] != DIMN * DIMN) wi++;
    const float* Wq = (const float*)d_in[wi + 0];
    const float* bq = (const float*)d_in[wi + 1];
    const float* Wk = (const float*)d_in[wi + 2];
    const float* bk = (const float*)d_in[wi + 3];
    const float* Wv = (const float*)d_in[wi + 4];
    const float* bv = (const float*)d_in[wi + 5];
    const float* Wo = (const float*)d_in[wi + 6];
    const float* bo = (const float*)d_in[wi + 7];
    float* out = (float*)d_out;

    h16 *ch, *cl, *wqh, *wql, *wkh, *wkl, *wvh, *woh, *wol;
    h16 *qh, *kh, *kl, *vh, *vl, *phh, *ahh;
    float* s;
    cudaGetSymbolAddress((void**)&ch, g_ch);   cudaGetSymbolAddress((void**)&cl, g_cl);
    cudaGetSymbolAddress((void**)&wqh, g_wqh); cudaGetSymbolAddress((void**)&wql, g_wql);
    cudaGetSymbolAddress((void**)&wkh, g_wkh); cudaGetSymbolAddress((void**)&wkl, g_wkl);
    cudaGetSymbolAddress((void**)&wvh, g_wvh);
    cudaGetSymbolAddress((void**)&woh, g_woh); cudaGetSymbolAddress((void**)&wol, g_wol);
    cudaGetSymbolAddress((void**)&qh, g_qh);
    cudaGetSymbolAddress((void**)&kh, g_kh);   cudaGetSymbolAddress((void**)&kl, g_kl);
    cudaGetSymbolAddress((void**)&vh, g_vh);   cudaGetSymbolAddress((void**)&vl, g_vl);
    cudaGetSymbolAddress((void**)&s, g_s);
    cudaGetSymbolAddress((void**)&phh, g_ph);
    cudaGetSymbolAddress((void**)&ahh, g_ah);

    cudaFuncSetAttribute(gemm_mma<1,1,0>, cudaFuncAttributeMaxDynamicSharedMemorySize, SMEM_MMA);
    cudaFuncSetAttribute(gemm_mma<2,1,0>, cudaFuncAttributeMaxDynamicSharedMemorySize, SMEM_MMA);
    cudaFuncSetAttribute(gemm_mma<2,2,0>, cudaFuncAttributeMaxDynamicSharedMemorySize, SMEM_MMA);
    cudaFuncSetAttribute(gemm_mma<0,0,1>, cudaFuncAttributeMaxDynamicSharedMemorySize, SMEM_MMA);
    cudaFuncSetAttribute(gemm_mma<1,0,2>, cudaFuncAttributeMaxDynamicSharedMemorySize, SMEM_MMA);
    cudaFuncSetAttribute(gemm_mma<0,1,0>, cudaFuncAttributeMaxDynamicSharedMemorySize, SMEM_MMA);

    const float scale = (float)(1.0 / sqrt((double)DIMN));

    // input conversions
    {
        size_t n4 = (size_t)BATCH * LQ * DIMN / 4;
        split_kernel<<<(unsigned)((n4 + 255) / 256), 256>>>(chunk, ch, cl, n4);
        size_t w4 = (size_t)DIMN * DIMN / 4;
        unsigned wg = (unsigned)((w4 + 255) / 256);
        split_kernel<<<wg, 256>>>(Wq, wqh, wql, w4);
        split_kernel<<<wg, 256>>>(Wk, wkh, wkl, w4);
        round_kernel<<<wg, 256>>>(Wv, wvh, w4);
        split_kernel<<<wg, 256>>>(Wo, woh, wol, w4);
        size_t ck4 = (size_t)BATCH * KC * DIMN / 4;
        cachek_kernel<<<(unsigned)((ck4 + 255) / 256), 256>>>(cached_k);
        cachev_kernel<<<dim3(KC / 32, DIMN / 32, BATCH), dim3(32, 8)>>>(cached_v);
    }

    // Q projection: chunk(hi) @ (Wq hi+lo)^T + bq -> Q hi-only
    gemm_mma<1,1,0><<<dim3(DIMN / BNT, (BATCH * LQ) / BMT, 1), 256, SMEM_MMA>>>(
        ch, wqh, wql, bq, nullptr, qh, nullptr,
        DIMN, DIMN, DIMN, DIMN, 0, 0, 0);

    // K projection -> k_full rows [KC, KT), hi+lo (K is B operand of S GEMM)
    gemm_mma<2,1,0><<<dim3(DIMN / BNT, LQ / BMT, BATCH), 256, SMEM_MMA>>>(
        ch, wkh, wkl, bk, nullptr, kh + (size_t)KC * DIMN, kl + (size_t)KC * DIMN,
        DIMN, DIMN, DIMN, DIMN,
        (long long)LQ * DIMN, 0, (long long)KTP * DIMN);

    // V^T projection: Wv(hi) @ (chunk hi+lo)^T + bv(row) -> vT cols [KC,KT), hi+lo
    gemm_mma<2,2,0><<<dim3(LQ / BNT, DIMN / BMT, BATCH), 256, SMEM_MMA>>>(
        wvh, ch, cl, bv, nullptr, vh + KC, vl + KC,
        DIMN, DIMN, DIMN, KT,
        0, (long long)LQ * DIMN, (long long)DIMN * KT);

    // S = Q(hi) @ (K hi+lo)^T (fp32 out; scale folded into softmax; masked tiles skipped)
    gemm_mma<0,0,1><<<dim3(KTP / BNT, LQ / BMT, BATCH), 256, SMEM_MMA>>>(
        qh, kh, kl, nullptr, s, nullptr, nullptr,
        DIMN, DIMN, DIMN, KTP,
        (long long)LQ * DIMN, (long long)KTP * DIMN, (long long)LQ * KTP);

    // masked softmax -> fp16 weights
    softmax_kernel<<<dim3(LQ, BATCH), 256>>>(s, phh, scale);

    // attended = P(hi) @ (V^T hi+lo), K loop clamped; heavy rows first; hi-only out
    gemm_mma<1,0,2><<<dim3(DIMN / BNT, LQ / BMT, BATCH), 256, SMEM_MMA>>>(
        phh, vh, vl, nullptr, nullptr, ahh, nullptr,
        KT, KT, KT, DIMN,
        (long long)LQ * KT, (long long)DIMN * KT, (long long)LQ * DIMN);

    // output projection: attended(hi) @ (Wo hi+lo)^T + bo -> fp32 out
    gemm_mma<0,1,0><<<dim3(DIMN / BNT, (BATCH * LQ) / BMT, 1), 256, SMEM_MMA>>>(
        ahh, woh, wol, bo, out, nullptr, nullptr,
        DIMN, DIMN, DIMN, DIMN, 0, 0, 0);
}

// round 9
// speedup vs baseline: 1.1013x; 1.1013x over previous
#include <cuda_runtime.h>
#include <cuda_fp16.h>
#include <math.h>
#include <stdint.h>

#define DIMN 2048
#define BATCH 4
#define LQ    4096
#define KC    576
#define KT    4672          // KC + LQ
#define KTP   4864          // padded N for the S GEMM (38*128)

typedef __half h16;

// ---------------------------------------------------------------------------
// Scratch (__device__ globals — zero-initialized; K rows [KT,KTP) stay 0)
// fp16 2-pass scheme: A operands stored hi-only, B operands hi+lo.
// ---------------------------------------------------------------------------
__device__ h16 g_ch [(size_t)BATCH*LQ*DIMN];   // chunk hi
__device__ h16 g_cl [(size_t)BATCH*LQ*DIMN];   // chunk lo
__device__ h16 g_wqh[(size_t)DIMN*DIMN], g_wql[(size_t)DIMN*DIMN];
__device__ h16 g_wkh[(size_t)DIMN*DIMN], g_wkl[(size_t)DIMN*DIMN];
__device__ h16 g_wvh[(size_t)DIMN*DIMN];
__device__ h16 g_woh[(size_t)DIMN*DIMN], g_wol[(size_t)DIMN*DIMN];
__device__ h16 g_qh [(size_t)BATCH*LQ*DIMN];
__device__ h16 g_kh [(size_t)BATCH*KTP*DIMN], g_kl[(size_t)BATCH*KTP*DIMN];
__device__ h16 g_vh [(size_t)BATCH*DIMN*KT],  g_vl[(size_t)BATCH*DIMN*KT]; // V^T [b][d][kt]
__device__ float g_s [(size_t)BATCH*LQ*KTP];
__device__ h16 g_ph [(size_t)BATCH*LQ*KT];
__device__ h16 g_ah [(size_t)BATCH*LQ*DIMN];

// ---------------------------------------------------------------------------
// helpers
// ---------------------------------------------------------------------------
__device__ __forceinline__ uint32_t s2u(const void* p) {
    uint32_t a;
    asm("{ .reg .u64 t; cvta.to.shared.u64 t, %1; cvt.u32.u64 %0, t; }" : "=r"(a) : "l"(p));
    return a;
}
__device__ __forceinline__ void cpa16(uint32_t d, const void* s) {
    asm volatile("cp.async.cg.shared.global [%0], [%1], 16;" :: "r"(d), "l"(s));
}
#define CP_COMMIT() asm volatile("cp.async.commit_group;" ::: "memory")
#define CP_WAIT1()  asm volatile("cp.async.wait_group 1;" ::: "memory")
#define CP_WAIT0()  asm volatile("cp.async.wait_group 0;" ::: "memory")

#define LDSM4(r, a) \
    asm volatile("ldmatrix.sync.aligned.m8n8.x4.shared.b16 {%0,%1,%2,%3}, [%4];" \
                 : "=r"((r)[0]), "=r"((r)[1]), "=r"((r)[2]), "=r"((r)[3]) : "r"(a))

__device__ __forceinline__ void mma16816(float* d, const uint32_t* a,
                                         uint32_t b0, uint32_t b1) {
    asm volatile(
        "mma.sync.aligned.m16n8k16.row.col.f32.f16.f16.f32 "
        "{%0,%1,%2,%3}, {%4,%5,%6,%7}, {%8,%9}, {%0,%1,%2,%3};"
        : "+f"(d[0]), "+f"(d[1]), "+f"(d[2]), "+f"(d[3])
        : "r"(a[0]), "r"(a[1]), "r"(a[2]), "r"(a[3]), "r"(b0), "r"(b1));
}

// x = hi(fp16) + lo(fp16); residual ~2^-22 |x|
__device__ __forceinline__ void split2h(float x0, float x1, uint32_t& h, uint32_t& l) {
    __half2 hp = __floats2half2_rn(x0, x1);
    float2 hf = __half22float2(hp);
    __half2 lp = __floats2half2_rn(x0 - hf.x, x1 - hf.y);
    h = *reinterpret_cast<uint32_t*>(&hp);
    l = *reinterpret_cast<uint32_t*>(&lp);
}
__device__ __forceinline__ uint32_t round2h(float x0, float x1) {
    __half2 hp = __floats2half2_rn(x0, x1);
    return *reinterpret_cast<uint32_t*>(&hp);
}

// ---------------------------------------------------------------------------
// fp16 2-pass mma.sync GEMM: C tile 128x128, BK=32, 3-stage cp.async pipeline,
// ONE __syncthreads per k-chunk. C = Ah·Bh^T + Ah·Bl^T. fp32 accum.
// A[M,K] hi-only, B[N,K] hi+lo, row-major (NT).
// OUTM: 0 fp32 out, 1 fp16 hi-only out, 2 fp16 hi+lo out.
// BIASM: 0 none, 1 bias[col], 2 bias[row]
// TRI:  0 none, 1 = skip block if col0 >= KC+row0+BMT (S GEMM),
//       2 = clamp K loop to KC+row0+BMT (AV GEMM; heavy rows scheduled first)
// ---------------------------------------------------------------------------
#define BMT 128
#define BNT 128
#define BKT 32
#define APAD 40                          // fp16 row stride (32+8) -> 80B
#define TILE_B (128 * APAD * 2)          // 10240 bytes per tile
#define STAGE_B (3 * TILE_B)             // Ah|Bh|Bl = 30720
#define SMEM_MMA (3 * STAGE_B)           // 92160 bytes (3 stages)

template<int OUTM, int BIASM, int TRI>
__global__ __launch_bounds__(256, 2)
void gemm_mma(const h16* __restrict__ Ah,
              const h16* __restrict__ Bh, const h16* __restrict__ Bl,
              const float* __restrict__ bias,
              float* __restrict__ Cf, h16* __restrict__ Ch, h16* __restrict__ Cl,
              int K, int lda, int ldb, int ldc,
              long long sA, long long sB, long long sC)
{
    // TRI==2: reverse row order so the heaviest (longest-K) CTAs start first
    const int row0 = (TRI == 2 ? (int)(gridDim.y - 1 - blockIdx.y) : (int)blockIdx.y) * BMT;
    const int col0 = blockIdx.x * BNT;
    if (TRI == 1 && col0 >= KC + row0 + BMT) return;   // fully-masked S tile

    extern __shared__ h16 sm[];
    const uint32_t smb = s2u(sm);
    const int tid  = threadIdx.x;
    const int lane = tid & 31, warp = tid >> 5;
    const int wm = warp & 1, wn = warp >> 1;    // warp grid 2 (M) x 4 (N)
    const size_t zA = (size_t)blockIdx.z * sA;
    const size_t zB = (size_t)blockIdx.z * sB;
    const size_t zC = (size_t)blockIdx.z * sC;

    int kchunks = K / BKT;
    if (TRI == 2) {
        int lim = (KC + row0 + BMT) / BKT;      // multiple of 32 by construction
        if (lim < kchunks) kchunks = lim;
    }

    // cp.async mapping: rows (tid>>2) and (tid>>2)+64, 16B chunk (tid&3)*8
    const int lrow = tid >> 2;
    const int lcol = (tid & 3) * 8;
    const uint32_t o1 = (lrow * APAD + lcol) * 2;
    const uint32_t o2 = ((lrow + 64) * APAD + lcol) * 2;

    auto issue = [&](int kc, int st) {
        const size_t ao = zA + (size_t)(row0 + lrow) * lda + (size_t)kc * BKT + lcol;
        const size_t bo = zB + (size_t)(col0 + lrow) * ldb + (size_t)kc * BKT + lcol;
        const uint32_t base = smb + st * STAGE_B;
        cpa16(base + o1,              Ah + ao);
        cpa16(base + o2,              Ah + ao + (size_t)64 * lda);
        cpa16(base + TILE_B + o1,     Bh + bo);
        cpa16(base + TILE_B + o2,     Bh + bo + (size_t)64 * ldb);
        cpa16(base + 2*TILE_B + o1,   Bl + bo);
        cpa16(base + 2*TILE_B + o2,   Bl + bo + (size_t)64 * ldb);
    };

    float acc[4][4][4];
#pragma unroll
    for (int i = 0; i < 4; i++)
#pragma unroll
        for (int j = 0; j < 4; j++)
#pragma unroll
            for (int e = 0; e < 4; e++) acc[i][j][e] = 0.f;

    // ldmatrix per-thread address components
    const int am = wm * 64 + (lane & 15);
    const int ak = (lane >> 4) * 8;
    const int bn = wn * 32 + (lane & 15);

    // prologue: fill 2 of the 3 stages
    issue(0, 0); CP_COMMIT();
    if (kchunks > 1) { issue(1, 1); CP_COMMIT(); }

    int st = 0;
    for (int kc = 0; kc < kchunks; ++kc) {
        // ensure group kc is complete
        if (kc + 1 < kchunks) CP_WAIT1(); else CP_WAIT0();
        __syncthreads();   // also covers the WAR hazard for stage (kc+2)%3

        // prefetch chunk kc+2 into the stage consumed at iteration kc-1
        if (kc + 2 < kchunks) {
            int st2 = st + 2; if (st2 >= 3) st2 -= 3;
            issue(kc + 2, st2);
            CP_COMMIT();
        }

        const uint32_t ah_ = smb + st * STAGE_B;
        const uint32_t bh_ = ah_ + TILE_B;
        const uint32_t bl_ = ah_ + 2 * TILE_B;
#pragma unroll
        for (int ks = 0; ks < 2; ks++) {
            uint32_t af[4][4], bh[2][4], bl[2][4];
            // load A(hi) + B(hi), run the hh group
#pragma unroll
            for (int mt = 0; mt < 4; mt++)
                LDSM4(af[mt], ah_ + (((am + mt * 16) * APAD) + ks * 16 + ak) * 2);
#pragma unroll
            for (int pr = 0; pr < 2; pr++)
                LDSM4(bh[pr], bh_ + (((bn + pr * 16) * APAD) + ks * 16 + ak) * 2);
#pragma unroll
            for (int mt = 0; mt < 4; mt++)
#pragma unroll
                for (int nt = 0; nt < 4; nt++)
                    mma16816(acc[mt][nt], af[mt],
                             bh[nt >> 1][nt & 1], bh[nt >> 1][(nt & 1) + 2]);
            // load B(lo) while hh drains, then hl group
#pragma unroll
            for (int pr = 0; pr < 2; pr++)
                LDSM4(bl[pr], bl_ + (((bn + pr * 16) * APAD) + ks * 16 + ak) * 2);
#pragma unroll
            for (int mt = 0; mt < 4; mt++)
#pragma unroll
                for (int nt = 0; nt < 4; nt++)
                    mma16816(acc[mt][nt], af[mt],
                             bl[nt >> 1][nt & 1], bl[nt >> 1][(nt & 1) + 2]);
        }
        if (++st == 3) st = 0;
    }

    // epilogue
    const int crow = lane >> 2;
    const int ccol = (lane & 3) * 2;
#pragma unroll
    for (int mt = 0; mt < 4; mt++) {
        const size_t r0g = (size_t)row0 + wm * 64 + mt * 16 + crow;
#pragma unroll
        for (int nt = 0; nt < 4; nt++) {
            const int cg = col0 + wn * 32 + nt * 8 + ccol;
            float v0 = acc[mt][nt][0], v1 = acc[mt][nt][1];
            float v2 = acc[mt][nt][2], v3 = acc[mt][nt][3];
            if (BIASM == 1) {
                const float b0 = bias[cg], b1 = bias[cg + 1];
                v0 += b0; v1 += b1; v2 += b0; v3 += b1;
            }
            if (BIASM == 2) {
                const float b0 = bias[r0g], b1 = bias[r0g + 8];
                v0 += b0; v1 += b0; v2 += b1; v3 += b1;
            }
            if (OUTM == 0) {
                *reinterpret_cast<float2*>(&Cf[zC + r0g * ldc + cg])       = make_float2(v0, v1);
                *reinterpret_cast<float2*>(&Cf[zC + (r0g + 8) * ldc + cg]) = make_float2(v2, v3);
            } else if (OUTM == 1) {
                *reinterpret_cast<uint32_t*>(&Ch[zC + r0g * ldc + cg])       = round2h(v0, v1);
                *reinterpret_cast<uint32_t*>(&Ch[zC + (r0g + 8) * ldc + cg]) = round2h(v2, v3);
            } else {
                uint32_t h, l;
                split2h(v0, v1, h, l);
                *reinterpret_cast<uint32_t*>(&Ch[zC + r0g * ldc + cg]) = h;
                *reinterpret_cast<uint32_t*>(&Cl[zC + r0g * ldc + cg]) = l;
                split2h(v2, v3, h, l);
                *reinterpret_cast<uint32_t*>(&Ch[zC + (r0g + 8) * ldc + cg]) = h;
                *reinterpret_cast<uint32_t*>(&Cl[zC + (r0g + 8) * ldc + cg]) = l;
            }
        }
    }
}

// ---------------------------------------------------------------------------
// Elementwise fp32 -> split fp16 (hi+lo) and fp32 -> fp16 (hi only)
// ---------------------------------------------------------------------------
__global__ void split_kernel(const float* __restrict__ src, h16* __restrict__ h,
                             h16* __restrict__ l, size_t n4)
{
    size_t i = (size_t)blockIdx.x * blockDim.x + threadIdx.x;
    if (i >= n4) return;
    float4 v = reinterpret_cast<const float4*>(src)[i];
    uint32_t h0, h1, l0, l1;
    split2h(v.x, v.y, h0, l0);
    split2h(v.z, v.w, h1, l1);
    reinterpret_cast<uint2*>(h)[i] = make_uint2(h0, h1);
    reinterpret_cast<uint2*>(l)[i] = make_uint2(l0, l1);
}

__global__ void round_kernel(const float* __restrict__ src, h16* __restrict__ h, size_t n4)
{
    size_t i = (size_t)blockIdx.x * blockDim.x + threadIdx.x;
    if (i >= n4) return;
    float4 v = reinterpret_cast<const float4*>(src)[i];
    reinterpret_cast<uint2*>(h)[i] = make_uint2(round2h(v.x, v.y), round2h(v.z, v.w));
}

__global__ void cachek_kernel(const float* __restrict__ ck)
{
    const size_t per = (size_t)KC * DIMN / 4;
    size_t i = (size_t)blockIdx.x * blockDim.x + threadIdx.x;
    if (i >= BATCH * per) return;
    size_t b = i / per, r = i - b * per;
    float4 v = reinterpret_cast<const float4*>(ck)[i];
    uint32_t h0, h1, l0, l1;
    split2h(v.x, v.y, h0, l0);
    split2h(v.z, v.w, h1, l1);
    size_t dst = b * ((size_t)KTP * DIMN / 4) + r;
    reinterpret_cast<uint2*>(g_kh)[dst] = make_uint2(h0, h1);
    reinterpret_cast<uint2*>(g_kl)[dst] = make_uint2(l0, l1);
}

// cached_v [B,KC,D] -> transposed split into g_vh/g_vl [B,D,KT] cols [0,KC)
__global__ void cachev_kernel(const float* __restrict__ cv)
{
    __shared__ float t[32][33];
    const int b = blockIdx.z;
    const int r0 = blockIdx.x * 32;   // kc
    const int c0 = blockIdx.y * 32;   // d
    const int tx = threadIdx.x, ty0 = threadIdx.y;
#pragma unroll
    for (int s = 0; s < 4; s++) {
        int ty = ty0 + s * 8;
        t[ty][tx] = cv[((size_t)b * KC + r0 + ty) * DIMN + c0 + tx];
    }
    __syncthreads();
#pragma unroll
    for (int s = 0; s < 4; s++) {
        int ty = ty0 + s * 8;
        float x = t[tx][ty];
        __half h = __float2half_rn(x);
        __half lo = __float2half_rn(x - __half2float(h));
        size_t o = ((size_t)b * DIMN + c0 + ty) * KT + r0 + tx;
        g_vh[o] = h;
        g_vl[o] = lo;
    }
}

// ---------------------------------------------------------------------------
// Masked softmax: row q sees [0, KC+q+1); emits fp16 weights (0 beyond).
// ---------------------------------------------------------------------------
__global__ void softmax_kernel(const float* __restrict__ S, h16* __restrict__ Wh,
                               float scale)
{
    __shared__ float sbuf[KT];
    __shared__ float red[256];
    const int q = blockIdx.x, b = blockIdx.y;
    const float* row = S + ((size_t)b * LQ + q) * KTP;
    h16* wh = Wh + ((size_t)b * LQ + q) * KT;
    const int valid = KC + q + 1;
    const int tid = threadIdx.x;

    float m = -1e30f;
    for (int c = tid; c < valid; c += 256) m = fmaxf(m, row[c] * scale);
    red[tid] = m; __syncthreads();
    for (int s = 128; s > 0; s >>= 1) { if (tid < s) red[tid] = fmaxf(red[tid], red[tid + s]); __syncthreads(); }
    m = red[0]; __syncthreads();

    float sum = 0.f;
    for (int c = tid; c < valid; c += 256) {
        float e = __expf(row[c] * scale - m);
        sbuf[c] = e;
        sum += e;
    }
    red[tid] = sum; __syncthreads();
    for (int s = 128; s > 0; s >>= 1) { if (tid < s) red[tid] += red[tid + s]; __syncthreads(); }
    const float inv = 1.f / red[0];
    __syncthreads();

    for (int c = tid; c < KT; c += 256)
        wh[c] = __float2half_rn((c < valid) ? sbuf[c] * inv : 0.f);
}

// ---------------------------------------------------------------------------
// kernel_launch
// ---------------------------------------------------------------------------
extern "C" void kernel_launch(void* const* d_in, const int* in_sizes, int n_in,
                              void* d_out, int out_size)
{
    const float* chunk    = (const float*)d_in[0];
    const float* cached_k = (const float*)d_in[1];
    const float* cached_v = (const float*)d_in[2];
    int wi = 3;
    while (wi < n_in && in_sizes[wi] != DIMN * DIMN) wi++;
    const float* Wq = (const float*)d_in[wi + 0];
    const float* bq = (const float*)d_in[wi + 1];
    const float* Wk = (const float*)d_in[wi + 2];
    const float* bk = (const float*)d_in[wi + 3];
    const float* Wv = (const float*)d_in[wi + 4];
    const float* bv = (const float*)d_in[wi + 5];
    const float* Wo = (const float*)d_in[wi + 6];
    const float* bo = (const float*)d_in[wi + 7];
    float* out = (float*)d_out;

    h16 *ch, *cl, *wqh, *wql, *wkh, *wkl, *wvh, *woh, *wol;
    h16 *qh, *kh, *kl, *vh, *vl, *phh, *ahh;
    float* s;
    cudaGetSymbolAddress((void**)&ch, g_ch);   cudaGetSymbolAddress((void**)&cl, g_cl);
    cudaGetSymbolAddress((void**)&wqh, g_wqh); cudaGetSymbolAddress((void**)&wql, g_wql);
    cudaGetSymbolAddress((void**)&wkh, g_wkh); cudaGetSymbolAddress((void**)&wkl, g_wkl);
    cudaGetSymbolAddress((void**)&wvh, g_wvh);
    cudaGetSymbolAddress((void**)&woh, g_woh); cudaGetSymbolAddress((void**)&wol, g_wol);
    cudaGetSymbolAddress((void**)&qh, g_qh);
    cudaGetSymbolAddress((void**)&kh, g_kh);   cudaGetSymbolAddress((void**)&kl, g_kl);
    cudaGetSymbolAddress((void**)&vh, g_vh);   cudaGetSymbolAddress((void**)&vl, g_vl);
    cudaGetSymbolAddress((void**)&s, g_s);
    cudaGetSymbolAddress((void**)&phh, g_ph);
    cudaGetSymbolAddress((void**)&ahh, g_ah);

    cudaFuncSetAttribute(gemm_mma<1,1,0>, cudaFuncAttributeMaxDynamicSharedMemorySize, SMEM_MMA);
    cudaFuncSetAttribute(gemm_mma<2,1,0>, cudaFuncAttributeMaxDynamicSharedMemorySize, SMEM_MMA);
    cudaFuncSetAttribute(gemm_mma<2,2,0>, cudaFuncAttributeMaxDynamicSharedMemorySize, SMEM_MMA);
    cudaFuncSetAttribute(gemm_mma<0,0,1>, cudaFuncAttributeMaxDynamicSharedMemorySize, SMEM_MMA);
    cudaFuncSetAttribute(gemm_mma<1,0,2>, cudaFuncAttributeMaxDynamicSharedMemorySize, SMEM_MMA);
    cudaFuncSetAttribute(gemm_mma<0,1,0>, cudaFuncAttributeMaxDynamicSharedMemorySize, SMEM_MMA);

    const float scale = (float)(1.0 / sqrt((double)DIMN));

    // input conversions
    {
        size_t n4 = (size_t)BATCH * LQ * DIMN / 4;
        split_kernel<<<(unsigned)((n4 + 255) / 256), 256>>>(chunk, ch, cl, n4);
        size_t w4 = (size_t)DIMN * DIMN / 4;
        unsigned wg = (unsigned)((w4 + 255) / 256);
        split_kernel<<<wg, 256>>>(Wq, wqh, wql, w4);
        split_kernel<<<wg, 256>>>(Wk, wkh, wkl, w4);
        round_kernel<<<wg, 256>>>(Wv, wvh, w4);
        split_kernel<<<wg, 256>>>(Wo, woh, wol, w4);
        size_t ck4 = (size_t)BATCH * KC * DIMN / 4;
        cachek_kernel<<<(unsigned)((ck4 + 255) / 256), 256>>>(cached_k);
        cachev_kernel<<<dim3(KC / 32, DIMN / 32, BATCH), dim3(32, 8)>>>(cached_v);
    }

    // Q projection: chunk(hi) @ (Wq hi+lo)^T + bq -> Q hi-only
    gemm_mma<1,1,0><<<dim3(DIMN / BNT, (BATCH * LQ) / BMT, 1), 256, SMEM_MMA>>>(
        ch, wqh, wql, bq, nullptr, qh, nullptr,
        DIMN, DIMN, DIMN, DIMN, 0, 0, 0);

    // K projection -> k_full rows [KC, KT), hi+lo (K is B operand of S GEMM)
    gemm_mma<2,1,0><<<dim3(DIMN / BNT, LQ / BMT, BATCH), 256, SMEM_MMA>>>(
        ch, wkh, wkl, bk, nullptr, kh + (size_t)KC * DIMN, kl + (size_t)KC * DIMN,
        DIMN, DIMN, DIMN, DIMN,
        (long long)LQ * DIMN, 0, (long long)KTP * DIMN);

    // V^T projection: Wv(hi) @ (chunk hi+lo)^T + bv(row) -> vT cols [KC,KT), hi+lo
    gemm_mma<2,2,0><<<dim3(LQ / BNT, DIMN / BMT, BATCH), 256, SMEM_MMA>>>(
        wvh, ch, cl, bv, nullptr, vh + KC, vl + KC,
        DIMN, DIMN, DIMN, KT,
        0, (long long)LQ * DIMN, (long long)DIMN * KT);

    // S = Q(hi) @ (K hi+lo)^T (fp32 out; scale folded into softmax; masked tiles skipped)
    gemm_mma<0,0,1><<<dim3(KTP / BNT, LQ / BMT, BATCH), 256, SMEM_MMA>>>(
        qh, kh, kl, nullptr, s, nullptr, nullptr,
        DIMN, DIMN, DIMN, KTP,
        (long long)LQ * DIMN, (long long)KTP * DIMN, (long long)LQ * KTP);

    // masked softmax -> fp16 weights
    softmax_kernel<<<dim3(LQ, BATCH), 256>>>(s, phh, scale);

    // attended = P(hi) @ (V^T hi+lo), K loop clamped; heavy rows first; hi-only out
    gemm_mma<1,0,2><<<dim3(DIMN / BNT, LQ / BMT, BATCH), 256, SMEM_MMA>>>(
        phh, vh, vl, nullptr, nullptr, ahh, nullptr,
        KT, KT, KT, DIMN,
        (long long)LQ * KT, (long long)DIMN * KT, (long long)LQ * DIMN);

    // output projection: attended(hi) @ (Wo hi+lo)^T + bo -> fp32 out
    gemm_mma<0,1,0><<<dim3(DIMN / BNT, (BATCH * LQ) / BMT, 1), 256, SMEM_MMA>>>(
        ahh, woh, wol, bo, out, nullptr, nullptr,
        DIMN, DIMN, DIMN, DIMN, 0, 0, 0);
}

// round 10
// speedup vs baseline: 1.1278x; 1.0241x over previous
#include <cuda_runtime.h>
#include <cuda_fp16.h>
#include <math.h>
#include <stdint.h>

#define DIMN 2048
#define BATCH 4
#define LQ    4096
#define KC    576
#define KT    4672          // KC + LQ
#define KTP   4864          // padded N for the S GEMM (38*128)

typedef __half h16;

// ---------------------------------------------------------------------------
// Scratch (__device__ globals — zero-initialized; K rows [KT,KTP) stay 0)
// fp16 2-pass scheme: A operands stored hi-only, B operands hi+lo.
// ---------------------------------------------------------------------------
__device__ h16 g_ch [(size_t)BATCH*LQ*DIMN];   // chunk hi
__device__ h16 g_cl [(size_t)BATCH*LQ*DIMN];   // chunk lo
__device__ h16 g_wqh[(size_t)DIMN*DIMN], g_wql[(size_t)DIMN*DIMN];
__device__ h16 g_wkh[(size_t)DIMN*DIMN], g_wkl[(size_t)DIMN*DIMN];
__device__ h16 g_wvh[(size_t)DIMN*DIMN];
__device__ h16 g_woh[(size_t)DIMN*DIMN], g_wol[(size_t)DIMN*DIMN];
__device__ h16 g_qh [(size_t)BATCH*LQ*DIMN];
__device__ h16 g_kh [(size_t)BATCH*KTP*DIMN], g_kl[(size_t)BATCH*KTP*DIMN];
__device__ h16 g_vh [(size_t)BATCH*DIMN*KT],  g_vl[(size_t)BATCH*DIMN*KT]; // V^T [b][d][kt]
__device__ float g_s [(size_t)BATCH*LQ*KTP];
__device__ h16 g_ph [(size_t)BATCH*LQ*KT];
__device__ h16 g_ah [(size_t)BATCH*LQ*DIMN];

// ---------------------------------------------------------------------------
// helpers
// ---------------------------------------------------------------------------
__device__ __forceinline__ uint32_t s2u(const void* p) {
    uint32_t a;
    asm("{ .reg .u64 t; cvta.to.shared.u64 t, %1; cvt.u32.u64 %0, t; }" : "=r"(a) : "l"(p));
    return a;
}
__device__ __forceinline__ void cpa16(uint32_t d, const void* s) {
    asm volatile("cp.async.cg.shared.global [%0], [%1], 16;" :: "r"(d), "l"(s));
}
#define CP_COMMIT() asm volatile("cp.async.commit_group;" ::: "memory")
#define CP_WAIT1()  asm volatile("cp.async.wait_group 1;" ::: "memory")
#define CP_WAIT0()  asm volatile("cp.async.wait_group 0;" ::: "memory")

#define LDSM4(r, a) \
    asm volatile("ldmatrix.sync.aligned.m8n8.x4.shared.b16 {%0,%1,%2,%3}, [%4];" \
                 : "=r"((r)[0]), "=r"((r)[1]), "=r"((r)[2]), "=r"((r)[3]) : "r"(a))

__device__ __forceinline__ void mma16816(float* d, const uint32_t* a,
                                         uint32_t b0, uint32_t b1) {
    asm volatile(
        "mma.sync.aligned.m16n8k16.row.col.f32.f16.f16.f32 "
        "{%0,%1,%2,%3}, {%4,%5,%6,%7}, {%8,%9}, {%0,%1,%2,%3};"
        : "+f"(d[0]), "+f"(d[1]), "+f"(d[2]), "+f"(d[3])
        : "r"(a[0]), "r"(a[1]), "r"(a[2]), "r"(a[3]), "r"(b0), "r"(b1));
}

// x = hi(fp16) + lo(fp16); residual ~2^-22 |x|
__device__ __forceinline__ void split2h(float x0, float x1, uint32_t& h, uint32_t& l) {
    __half2 hp = __floats2half2_rn(x0, x1);
    float2 hf = __half22float2(hp);
    __half2 lp = __floats2half2_rn(x0 - hf.x, x1 - hf.y);
    h = *reinterpret_cast<uint32_t*>(&hp);
    l = *reinterpret_cast<uint32_t*>(&lp);
}
__device__ __forceinline__ uint32_t round2h(float x0, float x1) {
    __half2 hp = __floats2half2_rn(x0, x1);
    return *reinterpret_cast<uint32_t*>(&hp);
}

// ---------------------------------------------------------------------------
// fp16 2-pass mma.sync GEMM: C tile 128x128, BK=32, 3-stage cp.async pipeline,
// ONE __syncthreads per k-chunk. C = Ah·Bh^T + Ah·Bl^T. fp32 accum.
// A[M,K] hi-only, B[N,K] hi+lo, row-major (NT).
// OUTM: 0 fp32 out, 1 fp16 hi-only out, 2 fp16 hi+lo out.
// BIASM: 0 none, 1 bias[col], 2 bias[row]
// TRI:  0 none, 1 = skip block if col0 >= KC+row0+BMT or col0 >= KT (S GEMM),
//       2 = clamp K loop to KC+row0+BMT (AV GEMM; heavy rows scheduled first)
// ---------------------------------------------------------------------------
#define BMT 128
#define BNT 128
#define BKT 32
#define APAD 40                          // fp16 row stride (32+8) -> 80B
#define TILE_B (128 * APAD * 2)          // 10240 bytes per tile
#define STAGE_B (3 * TILE_B)             // Ah|Bh|Bl = 30720
#define SMEM_MMA (3 * STAGE_B)           // 92160 bytes (3 stages)

template<int OUTM, int BIASM, int TRI>
__global__ __launch_bounds__(256, 2)
void gemm_mma(const h16* __restrict__ Ah,
              const h16* __restrict__ Bh, const h16* __restrict__ Bl,
              const float* __restrict__ bias,
              float* __restrict__ Cf, h16* __restrict__ Ch, h16* __restrict__ Cl,
              int K, int lda, int ldb, int ldc,
              long long sA, long long sB, long long sC)
{
    // TRI==2: reverse row order so the heaviest (longest-K) CTAs start first
    const int row0 = (TRI == 2 ? (int)(gridDim.y - 1 - blockIdx.y) : (int)blockIdx.y) * BMT;
    const int col0 = blockIdx.x * BNT;
    if (TRI == 1 && (col0 >= KC + row0 + BMT || col0 >= KT)) return; // masked / pad tile

    extern __shared__ h16 sm[];
    const uint32_t smb = s2u(sm);
    const int tid  = threadIdx.x;
    const int lane = tid & 31, warp = tid >> 5;
    const int wm = warp & 1, wn = warp >> 1;    // warp grid 2 (M) x 4 (N)
    const size_t zA = (size_t)blockIdx.z * sA;
    const size_t zB = (size_t)blockIdx.z * sB;
    const size_t zC = (size_t)blockIdx.z * sC;

    int kchunks = K / BKT;
    if (TRI == 2) {
        int lim = (KC + row0 + BMT) / BKT;      // multiple of 32 by construction
        if (lim < kchunks) kchunks = lim;
    }

    // cp.async mapping: rows (tid>>2) and (tid>>2)+64, 16B chunk (tid&3)*8
    const int lrow = tid >> 2;
    const int lcol = (tid & 3) * 8;
    const uint32_t o1 = (lrow * APAD + lcol) * 2;
    const uint32_t o2 = ((lrow + 64) * APAD + lcol) * 2;

    auto issue = [&](int kc, int st) {
        const size_t ao = zA + (size_t)(row0 + lrow) * lda + (size_t)kc * BKT + lcol;
        const size_t bo = zB + (size_t)(col0 + lrow) * ldb + (size_t)kc * BKT + lcol;
        const uint32_t base = smb + st * STAGE_B;
        cpa16(base + o1,              Ah + ao);
        cpa16(base + o2,              Ah + ao + (size_t)64 * lda);
        cpa16(base + TILE_B + o1,     Bh + bo);
        cpa16(base + TILE_B + o2,     Bh + bo + (size_t)64 * ldb);
        cpa16(base + 2*TILE_B + o1,   Bl + bo);
        cpa16(base + 2*TILE_B + o2,   Bl + bo + (size_t)64 * ldb);
    };

    float acc[4][4][4];
#pragma unroll
    for (int i = 0; i < 4; i++)
#pragma unroll
        for (int j = 0; j < 4; j++)
#pragma unroll
            for (int e = 0; e < 4; e++) acc[i][j][e] = 0.f;

    // ldmatrix per-thread address components
    const int am = wm * 64 + (lane & 15);
    const int ak = (lane >> 4) * 8;
    const int bn = wn * 32 + (lane & 15);

    // prologue: fill 2 of the 3 stages
    issue(0, 0); CP_COMMIT();
    if (kchunks > 1) { issue(1, 1); CP_COMMIT(); }

    int st = 0;
    for (int kc = 0; kc < kchunks; ++kc) {
        // ensure group kc is complete
        if (kc + 1 < kchunks) CP_WAIT1(); else CP_WAIT0();
        __syncthreads();   // also covers the WAR hazard for stage (kc+2)%3

        // prefetch chunk kc+2 into the stage consumed at iteration kc-1
        if (kc + 2 < kchunks) {
            int st2 = st + 2; if (st2 >= 3) st2 -= 3;
            issue(kc + 2, st2);
            CP_COMMIT();
        }

        const uint32_t ah_ = smb + st * STAGE_B;
        const uint32_t bh_ = ah_ + TILE_B;
        const uint32_t bl_ = ah_ + 2 * TILE_B;
#pragma unroll
        for (int ks = 0; ks < 2; ks++) {
            uint32_t af[4][4], bh[2][4], bl[2][4];
            // load A(hi) + B(hi), run the hh group
#pragma unroll
            for (int mt = 0; mt < 4; mt++)
                LDSM4(af[mt], ah_ + (((am + mt * 16) * APAD) + ks * 16 + ak) * 2);
#pragma unroll
            for (int pr = 0; pr < 2; pr++)
                LDSM4(bh[pr], bh_ + (((bn + pr * 16) * APAD) + ks * 16 + ak) * 2);
#pragma unroll
            for (int mt = 0; mt < 4; mt++)
#pragma unroll
                for (int nt = 0; nt < 4; nt++)
                    mma16816(acc[mt][nt], af[mt],
                             bh[nt >> 1][nt & 1], bh[nt >> 1][(nt & 1) + 2]);
            // load B(lo) while hh drains, then hl group
#pragma unroll
            for (int pr = 0; pr < 2; pr++)
                LDSM4(bl[pr], bl_ + (((bn + pr * 16) * APAD) + ks * 16 + ak) * 2);
#pragma unroll
            for (int mt = 0; mt < 4; mt++)
#pragma unroll
                for (int nt = 0; nt < 4; nt++)
                    mma16816(acc[mt][nt], af[mt],
                             bl[nt >> 1][nt & 1], bl[nt >> 1][(nt & 1) + 2]);
        }
        if (++st == 3) st = 0;
    }

    // epilogue
    const int crow = lane >> 2;
    const int ccol = (lane & 3) * 2;
#pragma unroll
    for (int mt = 0; mt < 4; mt++) {
        const size_t r0g = (size_t)row0 + wm * 64 + mt * 16 + crow;
#pragma unroll
        for (int nt = 0; nt < 4; nt++) {
            const int cg = col0 + wn * 32 + nt * 8 + ccol;
            float v0 = acc[mt][nt][0], v1 = acc[mt][nt][1];
            float v2 = acc[mt][nt][2], v3 = acc[mt][nt][3];
            if (BIASM == 1) {
                const float b0 = bias[cg], b1 = bias[cg + 1];
                v0 += b0; v1 += b1; v2 += b0; v3 += b1;
            }
            if (BIASM == 2) {
                const float b0 = bias[r0g], b1 = bias[r0g + 8];
                v0 += b0; v1 += b0; v2 += b1; v3 += b1;
            }
            if (OUTM == 0) {
                *reinterpret_cast<float2*>(&Cf[zC + r0g * ldc + cg])       = make_float2(v0, v1);
                *reinterpret_cast<float2*>(&Cf[zC + (r0g + 8) * ldc + cg]) = make_float2(v2, v3);
            } else if (OUTM == 1) {
                *reinterpret_cast<uint32_t*>(&Ch[zC + r0g * ldc + cg])       = round2h(v0, v1);
                *reinterpret_cast<uint32_t*>(&Ch[zC + (r0g + 8) * ldc + cg]) = round2h(v2, v3);
            } else {
                uint32_t h, l;
                split2h(v0, v1, h, l);
                *reinterpret_cast<uint32_t*>(&Ch[zC + r0g * ldc + cg]) = h;
                *reinterpret_cast<uint32_t*>(&Cl[zC + r0g * ldc + cg]) = l;
                split2h(v2, v3, h, l);
                *reinterpret_cast<uint32_t*>(&Ch[zC + (r0g + 8) * ldc + cg]) = h;
                *reinterpret_cast<uint32_t*>(&Cl[zC + (r0g + 8) * ldc + cg]) = l;
            }
        }
    }
}

// ---------------------------------------------------------------------------
// Elementwise fp32 -> split fp16 (hi+lo) and fp32 -> fp16 (hi only)
// ---------------------------------------------------------------------------
__global__ void split_kernel(const float* __restrict__ src, h16* __restrict__ h,
                             h16* __restrict__ l, size_t n4)
{
    size_t i = (size_t)blockIdx.x * blockDim.x + threadIdx.x;
    if (i >= n4) return;
    float4 v = reinterpret_cast<const float4*>(src)[i];
    uint32_t h0, h1, l0, l1;
    split2h(v.x, v.y, h0, l0);
    split2h(v.z, v.w, h1, l1);
    reinterpret_cast<uint2*>(h)[i] = make_uint2(h0, h1);
    reinterpret_cast<uint2*>(l)[i] = make_uint2(l0, l1);
}

__global__ void round_kernel(const float* __restrict__ src, h16* __restrict__ h, size_t n4)
{
    size_t i = (size_t)blockIdx.x * blockDim.x + threadIdx.x;
    if (i >= n4) return;
    float4 v = reinterpret_cast<const float4*>(src)[i];
    reinterpret_cast<uint2*>(h)[i] = make_uint2(round2h(v.x, v.y), round2h(v.z, v.w));
}

__global__ void cachek_kernel(const float* __restrict__ ck)
{
    const size_t per = (size_t)KC * DIMN / 4;
    size_t i = (size_t)blockIdx.x * blockDim.x + threadIdx.x;
    if (i >= BATCH * per) return;
    size_t b = i / per, r = i - b * per;
    float4 v = reinterpret_cast<const float4*>(ck)[i];
    uint32_t h0, h1, l0, l1;
    split2h(v.x, v.y, h0, l0);
    split2h(v.z, v.w, h1, l1);
    size_t dst = b * ((size_t)KTP * DIMN / 4) + r;
    reinterpret_cast<uint2*>(g_kh)[dst] = make_uint2(h0, h1);
    reinterpret_cast<uint2*>(g_kl)[dst] = make_uint2(l0, l1);
}

// cached_v [B,KC,D] -> transposed split into g_vh/g_vl [B,D,KT] cols [0,KC)
__global__ void cachev_kernel(const float* __restrict__ cv)
{
    __shared__ float t[32][33];
    const int b = blockIdx.z;
    const int r0 = blockIdx.x * 32;   // kc
    const int c0 = blockIdx.y * 32;   // d
    const int tx = threadIdx.x, ty0 = threadIdx.y;
#pragma unroll
    for (int s = 0; s < 4; s++) {
        int ty = ty0 + s * 8;
        t[ty][tx] = cv[((size_t)b * KC + r0 + ty) * DIMN + c0 + tx];
    }
    __syncthreads();
#pragma unroll
    for (int s = 0; s < 4; s++) {
        int ty = ty0 + s * 8;
        float x = t[tx][ty];
        __half h = __float2half_rn(x);
        __half lo = __float2half_rn(x - __half2float(h));
        size_t o = ((size_t)b * DIMN + c0 + ty) * KT + r0 + tx;
        g_vh[o] = h;
        g_vl[o] = lo;
    }
}

// ---------------------------------------------------------------------------
// Masked softmax: row q sees [0, KC+q+1); emits fp16 weights (0 beyond).
// ---------------------------------------------------------------------------
__global__ void softmax_kernel(const float* __restrict__ S, h16* __restrict__ Wh,
                               float scale)
{
    __shared__ float sbuf[KT];
    __shared__ float red[256];
    const int q = blockIdx.x, b = blockIdx.y;
    const float* row = S + ((size_t)b * LQ + q) * KTP;
    h16* wh = Wh + ((size_t)b * LQ + q) * KT;
    const int valid = KC + q + 1;
    const int tid = threadIdx.x;

    float m = -1e30f;
    for (int c = tid; c < valid; c += 256) m = fmaxf(m, row[c] * scale);
    red[tid] = m; __syncthreads();
    for (int s = 128; s > 0; s >>= 1) { if (tid < s) red[tid] = fmaxf(red[tid], red[tid + s]); __syncthreads(); }
    m = red[0]; __syncthreads();

    float sum = 0.f;
    for (int c = tid; c < valid; c += 256) {
        float e = __expf(row[c] * scale - m);
        sbuf[c] = e;
        sum += e;
    }
    red[tid] = sum; __syncthreads();
    for (int s = 128; s > 0; s >>= 1) { if (tid < s) red[tid] += red[tid + s]; __syncthreads(); }
    const float inv = 1.f / red[0];
    __syncthreads();

    for (int c = tid; c < KT; c += 256)
        wh[c] = __float2half_rn((c < valid) ? sbuf[c] * inv : 0.f);
}

// ---------------------------------------------------------------------------
// kernel_launch — graph captured with event-forked streams:
//   s0(default): conversions -> Q proj -> (wait K) S -> softmax -> (wait V) AV -> O
//   s1: cachek + K proj        s2: cachev + V^T proj (overlaps S/softmax)
// Streams/events are host-side handles created once; device work per call is
// identical and fully captured (fork via event wait, join via event wait).
// ---------------------------------------------------------------------------
extern "C" void kernel_launch(void* const* d_in, const int* in_sizes, int n_in,
                              void* d_out, int out_size)
{
    const float* chunk    = (const float*)d_in[0];
    const float* cached_k = (const float*)d_in[1];
    const float* cached_v = (const float*)d_in[2];
    int wi = 3;
    while (wi < n_in && in_sizes[wi] != DIMN * DIMN) wi++;
    const float* Wq = (const float*)d_in[wi + 0];
    const float* bq = (const float*)d_in[wi + 1];
    const float* Wk = (const float*)d_in[wi + 2];
    const float* bk = (const float*)d_in[wi + 3];
    const float* Wv = (const float*)d_in[wi + 4];
    const float* bv = (const float*)d_in[wi + 5];
    const float* Wo = (const float*)d_in[wi + 6];
    const float* bo = (const float*)d_in[wi + 7];
    float* out = (float*)d_out;

    h16 *ch, *cl, *wqh, *wql, *wkh, *wkl, *wvh, *woh, *wol;
    h16 *qh, *kh, *kl, *vh, *vl, *phh, *ahh;
    float* s;
    cudaGetSymbolAddress((void**)&ch, g_ch);   cudaGetSymbolAddress((void**)&cl, g_cl);
    cudaGetSymbolAddress((void**)&wqh, g_wqh); cudaGetSymbolAddress((void**)&wql, g_wql);
    cudaGetSymbolAddress((void**)&wkh, g_wkh); cudaGetSymbolAddress((void**)&wkl, g_wkl);
    cudaGetSymbolAddress((void**)&wvh, g_wvh);
    cudaGetSymbolAddress((void**)&woh, g_woh); cudaGetSymbolAddress((void**)&wol, g_wol);
    cudaGetSymbolAddress((void**)&qh, g_qh);
    cudaGetSymbolAddress((void**)&kh, g_kh);   cudaGetSymbolAddress((void**)&kl, g_kl);
    cudaGetSymbolAddress((void**)&vh, g_vh);   cudaGetSymbolAddress((void**)&vl, g_vl);
    cudaGetSymbolAddress((void**)&s, g_s);
    cudaGetSymbolAddress((void**)&phh, g_ph);
    cudaGetSymbolAddress((void**)&ahh, g_ah);

    cudaFuncSetAttribute(gemm_mma<1,1,0>, cudaFuncAttributeMaxDynamicSharedMemorySize, SMEM_MMA);
    cudaFuncSetAttribute(gemm_mma<2,1,0>, cudaFuncAttributeMaxDynamicSharedMemorySize, SMEM_MMA);
    cudaFuncSetAttribute(gemm_mma<2,2,0>, cudaFuncAttributeMaxDynamicSharedMemorySize, SMEM_MMA);
    cudaFuncSetAttribute(gemm_mma<0,0,1>, cudaFuncAttributeMaxDynamicSharedMemorySize, SMEM_MMA);
    cudaFuncSetAttribute(gemm_mma<1,0,2>, cudaFuncAttributeMaxDynamicSharedMemorySize, SMEM_MMA);
    cudaFuncSetAttribute(gemm_mma<0,1,0>, cudaFuncAttributeMaxDynamicSharedMemorySize, SMEM_MMA);

    // one-time host-side handles (no device memory involved)
    static cudaStream_t s1 = nullptr, s2 = nullptr;
    static cudaEvent_t e0 = nullptr, eK = nullptr, eV = nullptr;
    if (s1 == nullptr) {
        cudaStreamCreateWithFlags(&s1, cudaStreamNonBlocking);
        cudaStreamCreateWithFlags(&s2, cudaStreamNonBlocking);
        cudaEventCreateWithFlags(&e0, cudaEventDisableTiming);
        cudaEventCreateWithFlags(&eK, cudaEventDisableTiming);
        cudaEventCreateWithFlags(&eV, cudaEventDisableTiming);
    }

    const float scale = (float)(1.0 / sqrt((double)DIMN));

    // --- conversions on the capture (default) stream
    {
        size_t n4 = (size_t)BATCH * LQ * DIMN / 4;
        split_kernel<<<(unsigned)((n4 + 255) / 256), 256>>>(chunk, ch, cl, n4);
        size_t w4 = (size_t)DIMN * DIMN / 4;
        unsigned wg = (unsigned)((w4 + 255) / 256);
        split_kernel<<<wg, 256>>>(Wq, wqh, wql, w4);
        split_kernel<<<wg, 256>>>(Wk, wkh, wkl, w4);
        round_kernel<<<wg, 256>>>(Wv, wvh, w4);
        split_kernel<<<wg, 256>>>(Wo, woh, wol, w4);
    }
    cudaEventRecord(e0, 0);
    cudaStreamWaitEvent(s1, e0, 0);
    cudaStreamWaitEvent(s2, e0, 0);

    // --- s1: cached K + K projection
    {
        size_t ck4 = (size_t)BATCH * KC * DIMN / 4;
        cachek_kernel<<<(unsigned)((ck4 + 255) / 256), 256, 0, s1>>>(cached_k);
        gemm_mma<2,1,0><<<dim3(DIMN / BNT, LQ / BMT, BATCH), 256, SMEM_MMA, s1>>>(
            ch, wkh, wkl, bk, nullptr, kh + (size_t)KC * DIMN, kl + (size_t)KC * DIMN,
            DIMN, DIMN, DIMN, DIMN,
            (long long)LQ * DIMN, 0, (long long)KTP * DIMN);
        cudaEventRecord(eK, s1);
    }

    // --- s2: cached V + V^T projection (overlaps Q proj, S GEMM, softmax)
    {
        cachev_kernel<<<dim3(KC / 32, DIMN / 32, BATCH), dim3(32, 8), 0, s2>>>(cached_v);
        gemm_mma<2,2,0><<<dim3(LQ / BNT, DIMN / BMT, BATCH), 256, SMEM_MMA, s2>>>(
            wvh, ch, cl, bv, nullptr, vh + KC, vl + KC,
            DIMN, DIMN, DIMN, KT,
            0, (long long)LQ * DIMN, (long long)DIMN * KT);
        cudaEventRecord(eV, s2);
    }

    // --- s0: Q projection
    gemm_mma<1,1,0><<<dim3(DIMN / BNT, (BATCH * LQ) / BMT, 1), 256, SMEM_MMA>>>(
        ch, wqh, wql, bq, nullptr, qh, nullptr,
        DIMN, DIMN, DIMN, DIMN, 0, 0, 0);

    // join K, then S = Q @ K^T
    cudaStreamWaitEvent(0, eK, 0);
    gemm_mma<0,0,1><<<dim3(KTP / BNT, LQ / BMT, BATCH), 256, SMEM_MMA>>>(
        qh, kh, kl, nullptr, s, nullptr, nullptr,
        DIMN, DIMN, DIMN, KTP,
        (long long)LQ * DIMN, (long long)KTP * DIMN, (long long)LQ * KTP);

    // masked softmax -> fp16 weights
    softmax_kernel<<<dim3(LQ, BATCH), 256>>>(s, phh, scale);

    // join V, then attended = P @ V (K loop clamped; heavy rows first)
    cudaStreamWaitEvent(0, eV, 0);
    gemm_mma<1,0,2><<<dim3(DIMN / BNT, LQ / BMT, BATCH), 256, SMEM_MMA>>>(
        phh, vh, vl, nullptr, nullptr, ahh, nullptr,
        KT, KT, KT, DIMN,
        (long long)LQ * KT, (long long)DIMN * KT, (long long)LQ * DIMN);

    // output projection: attended(hi) @ (Wo hi+lo)^T + bo -> fp32 out
    gemm_mma<0,1,0><<<dim3(DIMN / BNT, (BATCH * LQ) / BMT, 1), 256, SMEM_MMA>>>(
        ahh, woh, wol, bo, out, nullptr, nullptr,
        DIMN, DIMN, DIMN, DIMN, 0, 0, 0);
}

// round 11
// speedup vs baseline: 1.4030x; 1.2440x over previous
#include <cuda_runtime.h>
#include <cuda_fp16.h>
#include <math.h>
#include <stdint.h>

#define DIMN 2048
#define BATCH 4
#define LQ    4096
#define KC    576
#define KT    4672          // KC + LQ
#define KTP   4864          // padded N for the S GEMM (38*128)

typedef __half h16;

// ---------------------------------------------------------------------------
// Scratch (__device__ globals — zero-initialized; K rows [KT,KTP) stay 0)
// fp16 scheme: A operands hi-only; B operands hi+lo ONLY where softmax can
// amplify the error (Q/K projections, S). V / AV / O run single-pass.
// ---------------------------------------------------------------------------
__device__ h16 g_ch [(size_t)BATCH*LQ*DIMN];   // chunk hi
__device__ h16 g_cl [(size_t)BATCH*LQ*DIMN];   // chunk lo
__device__ h16 g_wqh[(size_t)DIMN*DIMN], g_wql[(size_t)DIMN*DIMN];
__device__ h16 g_wkh[(size_t)DIMN*DIMN], g_wkl[(size_t)DIMN*DIMN];
__device__ h16 g_wvh[(size_t)DIMN*DIMN];
__device__ h16 g_woh[(size_t)DIMN*DIMN];
__device__ h16 g_qh [(size_t)BATCH*LQ*DIMN];
__device__ h16 g_kh [(size_t)BATCH*KTP*DIMN], g_kl[(size_t)BATCH*KTP*DIMN];
__device__ h16 g_vh [(size_t)BATCH*DIMN*KT];   // V^T [b][d][kt], hi only
__device__ float g_s [(size_t)BATCH*LQ*KTP];
__device__ h16 g_ph [(size_t)BATCH*LQ*KT];
__device__ h16 g_ah [(size_t)BATCH*LQ*DIMN];

// ---------------------------------------------------------------------------
// helpers
// ---------------------------------------------------------------------------
__device__ __forceinline__ uint32_t s2u(const void* p) {
    uint32_t a;
    asm("{ .reg .u64 t; cvta.to.shared.u64 t, %1; cvt.u32.u64 %0, t; }" : "=r"(a) : "l"(p));
    return a;
}
__device__ __forceinline__ void cpa16(uint32_t d, const void* s) {
    asm volatile("cp.async.cg.shared.global [%0], [%1], 16;" :: "r"(d), "l"(s));
}
#define CP_COMMIT() asm volatile("cp.async.commit_group;" ::: "memory")
#define CP_WAIT1()  asm volatile("cp.async.wait_group 1;" ::: "memory")
#define CP_WAIT0()  asm volatile("cp.async.wait_group 0;" ::: "memory")

#define LDSM4(r, a) \
    asm volatile("ldmatrix.sync.aligned.m8n8.x4.shared.b16 {%0,%1,%2,%3}, [%4];" \
                 : "=r"((r)[0]), "=r"((r)[1]), "=r"((r)[2]), "=r"((r)[3]) : "r"(a))

__device__ __forceinline__ void mma16816(float* d, const uint32_t* a,
                                         uint32_t b0, uint32_t b1) {
    asm volatile(
        "mma.sync.aligned.m16n8k16.row.col.f32.f16.f16.f32 "
        "{%0,%1,%2,%3}, {%4,%5,%6,%7}, {%8,%9}, {%0,%1,%2,%3};"
        : "+f"(d[0]), "+f"(d[1]), "+f"(d[2]), "+f"(d[3])
        : "r"(a[0]), "r"(a[1]), "r"(a[2]), "r"(a[3]), "r"(b0), "r"(b1));
}

// x = hi(fp16) + lo(fp16); residual ~2^-22 |x|
__device__ __forceinline__ void split2h(float x0, float x1, uint32_t& h, uint32_t& l) {
    __half2 hp = __floats2half2_rn(x0, x1);
    float2 hf = __half22float2(hp);
    __half2 lp = __floats2half2_rn(x0 - hf.x, x1 - hf.y);
    h = *reinterpret_cast<uint32_t*>(&hp);
    l = *reinterpret_cast<uint32_t*>(&lp);
}
__device__ __forceinline__ uint32_t round2h(float x0, float x1) {
    __half2 hp = __floats2half2_rn(x0, x1);
    return *reinterpret_cast<uint32_t*>(&hp);
}

// ---------------------------------------------------------------------------
// fp16 mma.sync GEMM: C tile 128x128, BK=32, 3-stage cp.async pipeline,
// ONE __syncthreads per k-chunk. fp32 accum.
// TWOPASS=1: C = Ah·Bh^T + Ah·Bl^T;  TWOPASS=0: C = Ah·Bh^T (Bl ignored).
// A[M,K] hi-only, B[N,K], row-major (NT).
// OUTM: 0 fp32 out, 1 fp16 hi-only out, 2 fp16 hi+lo out.
// BIASM: 0 none, 1 bias[col], 2 bias[row]
// TRI:  0 none, 1 = skip block if col0 >= KC+row0+BMT or col0 >= KT (S GEMM),
//       2 = clamp K loop to KC+row0+BMT (AV GEMM; heavy rows scheduled first)
// ---------------------------------------------------------------------------
#define BMT 128
#define BNT 128
#define BKT 32
#define APAD 40                          // fp16 row stride (32+8) -> 80B
#define TILE_B (128 * APAD * 2)          // 10240 bytes per tile
#define STAGE_B (3 * TILE_B)             // Ah|Bh|Bl = 30720
#define SMEM_MMA (3 * STAGE_B)           // 92160 bytes (3 stages)

template<int OUTM, int BIASM, int TRI, int TWOPASS>
__global__ __launch_bounds__(256, 2)
void gemm_mma(const h16* __restrict__ Ah,
              const h16* __restrict__ Bh, const h16* __restrict__ Bl,
              const float* __restrict__ bias,
              float* __restrict__ Cf, h16* __restrict__ Ch, h16* __restrict__ Cl,
              int K, int lda, int ldb, int ldc,
              long long sA, long long sB, long long sC)
{
    // TRI==2: reverse row order so the heaviest (longest-K) CTAs start first
    const int row0 = (TRI == 2 ? (int)(gridDim.y - 1 - blockIdx.y) : (int)blockIdx.y) * BMT;
    const int col0 = blockIdx.x * BNT;
    if (TRI == 1 && (col0 >= KC + row0 + BMT || col0 >= KT)) return; // masked / pad tile

    extern __shared__ h16 sm[];
    const uint32_t smb = s2u(sm);
    const int tid  = threadIdx.x;
    const int lane = tid & 31, warp = tid >> 5;
    const int wm = warp & 1, wn = warp >> 1;    // warp grid 2 (M) x 4 (N)
    const size_t zA = (size_t)blockIdx.z * sA;
    const size_t zB = (size_t)blockIdx.z * sB;
    const size_t zC = (size_t)blockIdx.z * sC;

    int kchunks = K / BKT;
    if (TRI == 2) {
        int lim = (KC + row0 + BMT) / BKT;      // multiple of 32 by construction
        if (lim < kchunks) kchunks = lim;
    }

    // cp.async mapping: rows (tid>>2) and (tid>>2)+64, 16B chunk (tid&3)*8
    const int lrow = tid >> 2;
    const int lcol = (tid & 3) * 8;
    const uint32_t o1 = (lrow * APAD + lcol) * 2;
    const uint32_t o2 = ((lrow + 64) * APAD + lcol) * 2;

    auto issue = [&](int kc, int st) {
        const size_t ao = zA + (size_t)(row0 + lrow) * lda + (size_t)kc * BKT + lcol;
        const size_t bo = zB + (size_t)(col0 + lrow) * ldb + (size_t)kc * BKT + lcol;
        const uint32_t base = smb + st * STAGE_B;
        cpa16(base + o1,              Ah + ao);
        cpa16(base + o2,              Ah + ao + (size_t)64 * lda);
        cpa16(base + TILE_B + o1,     Bh + bo);
        cpa16(base + TILE_B + o2,     Bh + bo + (size_t)64 * ldb);
        if (TWOPASS) {
            cpa16(base + 2*TILE_B + o1, Bl + bo);
            cpa16(base + 2*TILE_B + o2, Bl + bo + (size_t)64 * ldb);
        }
    };

    float acc[4][4][4];
#pragma unroll
    for (int i = 0; i < 4; i++)
#pragma unroll
        for (int j = 0; j < 4; j++)
#pragma unroll
            for (int e = 0; e < 4; e++) acc[i][j][e] = 0.f;

    // ldmatrix per-thread address components
    const int am = wm * 64 + (lane & 15);
    const int ak = (lane >> 4) * 8;
    const int bn = wn * 32 + (lane & 15);

    // prologue: fill 2 of the 3 stages
    issue(0, 0); CP_COMMIT();
    if (kchunks > 1) { issue(1, 1); CP_COMMIT(); }

    int st = 0;
    for (int kc = 0; kc < kchunks; ++kc) {
        // ensure group kc is complete
        if (kc + 1 < kchunks) CP_WAIT1(); else CP_WAIT0();
        __syncthreads();   // also covers the WAR hazard for stage (kc+2)%3

        // prefetch chunk kc+2 into the stage consumed at iteration kc-1
        if (kc + 2 < kchunks) {
            int st2 = st + 2; if (st2 >= 3) st2 -= 3;
            issue(kc + 2, st2);
            CP_COMMIT();
        }

        const uint32_t ah_ = smb + st * STAGE_B;
        const uint32_t bh_ = ah_ + TILE_B;
        const uint32_t bl_ = ah_ + 2 * TILE_B;
#pragma unroll
        for (int ks = 0; ks < 2; ks++) {
            uint32_t af[4][4], bh[2][4], bl[2][4];
            // load A(hi) + B(hi), run the hh group
#pragma unroll
            for (int mt = 0; mt < 4; mt++)
                LDSM4(af[mt], ah_ + (((am + mt * 16) * APAD) + ks * 16 + ak) * 2);
#pragma unroll
            for (int pr = 0; pr < 2; pr++)
                LDSM4(bh[pr], bh_ + (((bn + pr * 16) * APAD) + ks * 16 + ak) * 2);
#pragma unroll
            for (int mt = 0; mt < 4; mt++)
#pragma unroll
                for (int nt = 0; nt < 4; nt++)
                    mma16816(acc[mt][nt], af[mt],
                             bh[nt >> 1][nt & 1], bh[nt >> 1][(nt & 1) + 2]);
            if (TWOPASS) {
                // load B(lo) while hh drains, then hl group
#pragma unroll
                for (int pr = 0; pr < 2; pr++)
                    LDSM4(bl[pr], bl_ + (((bn + pr * 16) * APAD) + ks * 16 + ak) * 2);
#pragma unroll
                for (int mt = 0; mt < 4; mt++)
#pragma unroll
                    for (int nt = 0; nt < 4; nt++)
                        mma16816(acc[mt][nt], af[mt],
                                 bl[nt >> 1][nt & 1], bl[nt >> 1][(nt & 1) + 2]);
            }
        }
        if (++st == 3) st = 0;
    }

    // epilogue
    const int crow = lane >> 2;
    const int ccol = (lane & 3) * 2;
#pragma unroll
    for (int mt = 0; mt < 4; mt++) {
        const size_t r0g = (size_t)row0 + wm * 64 + mt * 16 + crow;
#pragma unroll
        for (int nt = 0; nt < 4; nt++) {
            const int cg = col0 + wn * 32 + nt * 8 + ccol;
            float v0 = acc[mt][nt][0], v1 = acc[mt][nt][1];
            float v2 = acc[mt][nt][2], v3 = acc[mt][nt][3];
            if (BIASM == 1) {
                const float b0 = bias[cg], b1 = bias[cg + 1];
                v0 += b0; v1 += b1; v2 += b0; v3 += b1;
            }
            if (BIASM == 2) {
                const float b0 = bias[r0g], b1 = bias[r0g + 8];
                v0 += b0; v1 += b0; v2 += b1; v3 += b1;
            }
            if (OUTM == 0) {
                *reinterpret_cast<float2*>(&Cf[zC + r0g * ldc + cg])       = make_float2(v0, v1);
                *reinterpret_cast<float2*>(&Cf[zC + (r0g + 8) * ldc + cg]) = make_float2(v2, v3);
            } else if (OUTM == 1) {
                *reinterpret_cast<uint32_t*>(&Ch[zC + r0g * ldc + cg])       = round2h(v0, v1);
                *reinterpret_cast<uint32_t*>(&Ch[zC + (r0g + 8) * ldc + cg]) = round2h(v2, v3);
            } else {
                uint32_t h, l;
                split2h(v0, v1, h, l);
                *reinterpret_cast<uint32_t*>(&Ch[zC + r0g * ldc + cg]) = h;
                *reinterpret_cast<uint32_t*>(&Cl[zC + r0g * ldc + cg]) = l;
                split2h(v2, v3, h, l);
                *reinterpret_cast<uint32_t*>(&Ch[zC + (r0g + 8) * ldc + cg]) = h;
                *reinterpret_cast<uint32_t*>(&Cl[zC + (r0g + 8) * ldc + cg]) = l;
            }
        }
    }
}

// ---------------------------------------------------------------------------
// Elementwise fp32 -> split fp16 (hi+lo) and fp32 -> fp16 (hi only)
// ---------------------------------------------------------------------------
__global__ void split_kernel(const float* __restrict__ src, h16* __restrict__ h,
                             h16* __restrict__ l, size_t n4)
{
    size_t i = (size_t)blockIdx.x * blockDim.x + threadIdx.x;
    if (i >= n4) return;
    float4 v = reinterpret_cast<const float4*>(src)[i];
    uint32_t h0, h1, l0, l1;
    split2h(v.x, v.y, h0, l0);
    split2h(v.z, v.w, h1, l1);
    reinterpret_cast<uint2*>(h)[i] = make_uint2(h0, h1);
    reinterpret_cast<uint2*>(l)[i] = make_uint2(l0, l1);
}

__global__ void round_kernel(const float* __restrict__ src, h16* __restrict__ h, size_t n4)
{
    size_t i = (size_t)blockIdx.x * blockDim.x + threadIdx.x;
    if (i >= n4) return;
    float4 v = reinterpret_cast<const float4*>(src)[i];
    reinterpret_cast<uint2*>(h)[i] = make_uint2(round2h(v.x, v.y), round2h(v.z, v.w));
}

__global__ void cachek_kernel(const float* __restrict__ ck)
{
    const size_t per = (size_t)KC * DIMN / 4;
    size_t i = (size_t)blockIdx.x * blockDim.x + threadIdx.x;
    if (i >= BATCH * per) return;
    size_t b = i / per, r = i - b * per;
    float4 v = reinterpret_cast<const float4*>(ck)[i];
    uint32_t h0, h1, l0, l1;
    split2h(v.x, v.y, h0, l0);
    split2h(v.z, v.w, h1, l1);
    size_t dst = b * ((size_t)KTP * DIMN / 4) + r;
    reinterpret_cast<uint2*>(g_kh)[dst] = make_uint2(h0, h1);
    reinterpret_cast<uint2*>(g_kl)[dst] = make_uint2(l0, l1);
}

// cached_v [B,KC,D] -> transposed (hi only) into g_vh [B,D,KT] cols [0,KC)
__global__ void cachev_kernel(const float* __restrict__ cv)
{
    __shared__ float t[32][33];
    const int b = blockIdx.z;
    const int r0 = blockIdx.x * 32;   // kc
    const int c0 = blockIdx.y * 32;   // d
    const int tx = threadIdx.x, ty0 = threadIdx.y;
#pragma unroll
    for (int s = 0; s < 4; s++) {
        int ty = ty0 + s * 8;
        t[ty][tx] = cv[((size_t)b * KC + r0 + ty) * DIMN + c0 + tx];
    }
    __syncthreads();
#pragma unroll
    for (int s = 0; s < 4; s++) {
        int ty = ty0 + s * 8;
        size_t o = ((size_t)b * DIMN + c0 + ty) * KT + r0 + tx;
        g_vh[o] = __float2half_rn(t[tx][ty]);
    }
}

// ---------------------------------------------------------------------------
// Masked softmax: row q sees [0, KC+q+1); emits fp16 weights (0 beyond).
// ---------------------------------------------------------------------------
__global__ void softmax_kernel(const float* __restrict__ S, h16* __restrict__ Wh,
                               float scale)
{
    __shared__ float sbuf[KT];
    __shared__ float red[256];
    const int q = blockIdx.x, b = blockIdx.y;
    const float* row = S + ((size_t)b * LQ + q) * KTP;
    h16* wh = Wh + ((size_t)b * LQ + q) * KT;
    const int valid = KC + q + 1;
    const int tid = threadIdx.x;

    float m = -1e30f;
    for (int c = tid; c < valid; c += 256) m = fmaxf(m, row[c] * scale);
    red[tid] = m; __syncthreads();
    for (int s = 128; s > 0; s >>= 1) { if (tid < s) red[tid] = fmaxf(red[tid], red[tid + s]); __syncthreads(); }
    m = red[0]; __syncthreads();

    float sum = 0.f;
    for (int c = tid; c < valid; c += 256) {
        float e = __expf(row[c] * scale - m);
        sbuf[c] = e;
        sum += e;
    }
    red[tid] = sum; __syncthreads();
    for (int s = 128; s > 0; s >>= 1) { if (tid < s) red[tid] += red[tid + s]; __syncthreads(); }
    const float inv = 1.f / red[0];
    __syncthreads();

    for (int c = tid; c < KT; c += 256)
        wh[c] = __float2half_rn((c < valid) ? sbuf[c] * inv : 0.f);
}

// ---------------------------------------------------------------------------
// kernel_launch — graph captured with event-forked streams:
//   s0(default): conversions -> Q proj -> (wait K) S -> softmax -> (wait V) AV -> O
//   s1: cachek + K proj        s2: cachev + V^T proj (overlaps S/softmax)
// ---------------------------------------------------------------------------
extern "C" void kernel_launch(void* const* d_in, const int* in_sizes, int n_in,
                              void* d_out, int out_size)
{
    const float* chunk    = (const float*)d_in[0];
    const float* cached_k = (const float*)d_in[1];
    const float* cached_v = (const float*)d_in[2];
    int wi = 3;
    while (wi < n_in && in_sizes[wi] != DIMN * DIMN) wi++;
    const float* Wq = (const float*)d_in[wi + 0];
    const float* bq = (const float*)d_in[wi + 1];
    const float* Wk = (const float*)d_in[wi + 2];
    const float* bk = (const float*)d_in[wi + 3];
    const float* Wv = (const float*)d_in[wi + 4];
    const float* bv = (const float*)d_in[wi + 5];
    const float* Wo = (const float*)d_in[wi + 6];
    const float* bo = (const float*)d_in[wi + 7];
    float* out = (float*)d_out;

    h16 *ch, *cl, *wqh, *wql, *wkh, *wkl, *wvh, *woh;
    h16 *qh, *kh, *kl, *vh, *phh, *ahh;
    float* s;
    cudaGetSymbolAddress((void**)&ch, g_ch);   cudaGetSymbolAddress((void**)&cl, g_cl);
    cudaGetSymbolAddress((void**)&wqh, g_wqh); cudaGetSymbolAddress((void**)&wql, g_wql);
    cudaGetSymbolAddress((void**)&wkh, g_wkh); cudaGetSymbolAddress((void**)&wkl, g_wkl);
    cudaGetSymbolAddress((void**)&wvh, g_wvh);
    cudaGetSymbolAddress((void**)&woh, g_woh);
    cudaGetSymbolAddress((void**)&qh, g_qh);
    cudaGetSymbolAddress((void**)&kh, g_kh);   cudaGetSymbolAddress((void**)&kl, g_kl);
    cudaGetSymbolAddress((void**)&vh, g_vh);
    cudaGetSymbolAddress((void**)&s, g_s);
    cudaGetSymbolAddress((void**)&phh, g_ph);
    cudaGetSymbolAddress((void**)&ahh, g_ah);

    cudaFuncSetAttribute(gemm_mma<1,1,0,1>, cudaFuncAttributeMaxDynamicSharedMemorySize, SMEM_MMA);
    cudaFuncSetAttribute(gemm_mma<2,1,0,1>, cudaFuncAttributeMaxDynamicSharedMemorySize, SMEM_MMA);
    cudaFuncSetAttribute(gemm_mma<1,2,0,0>, cudaFuncAttributeMaxDynamicSharedMemorySize, SMEM_MMA);
    cudaFuncSetAttribute(gemm_mma<0,0,1,1>, cudaFuncAttributeMaxDynamicSharedMemorySize, SMEM_MMA);
    cudaFuncSetAttribute(gemm_mma<1,0,2,0>, cudaFuncAttributeMaxDynamicSharedMemorySize, SMEM_MMA);
    cudaFuncSetAttribute(gemm_mma<0,1,0,0>, cudaFuncAttributeMaxDynamicSharedMemorySize, SMEM_MMA);

    // one-time host-side handles (no device memory involved)
    static cudaStream_t s1 = nullptr, s2 = nullptr;
    static cudaEvent_t e0 = nullptr, eK = nullptr, eV = nullptr;
    if (s1 == nullptr) {
        cudaStreamCreateWithFlags(&s1, cudaStreamNonBlocking);
        cudaStreamCreateWithFlags(&s2, cudaStreamNonBlocking);
        cudaEventCreateWithFlags(&e0, cudaEventDisableTiming);
        cudaEventCreateWithFlags(&eK, cudaEventDisableTiming);
        cudaEventCreateWithFlags(&eV, cudaEventDisableTiming);
    }

    const float scale = (float)(1.0 / sqrt((double)DIMN));

    // --- conversions on the capture (default) stream
    {
        size_t n4 = (size_t)BATCH * LQ * DIMN / 4;
        split_kernel<<<(unsigned)((n4 + 255) / 256), 256>>>(chunk, ch, cl, n4);
        size_t w4 = (size_t)DIMN * DIMN / 4;
        unsigned wg = (unsigned)((w4 + 255) / 256);
        split_kernel<<<wg, 256>>>(Wq, wqh, wql, w4);
        split_kernel<<<wg, 256>>>(Wk, wkh, wkl, w4);
        round_kernel<<<wg, 256>>>(Wv, wvh, w4);
        round_kernel<<<wg, 256>>>(Wo, woh, w4);
    }
    cudaEventRecord(e0, 0);
    cudaStreamWaitEvent(s1, e0, 0);
    cudaStreamWaitEvent(s2, e0, 0);

    // --- s1: cached K + K projection (2-pass)
    {
        size_t ck4 = (size_t)BATCH * KC * DIMN / 4;
        cachek_kernel<<<(unsigned)((ck4 + 255) / 256), 256, 0, s1>>>(cached_k);
        gemm_mma<2,1,0,1><<<dim3(DIMN / BNT, LQ / BMT, BATCH), 256, SMEM_MMA, s1>>>(
            ch, wkh, wkl, bk, nullptr, kh + (size_t)KC * DIMN, kl + (size_t)KC * DIMN,
            DIMN, DIMN, DIMN, DIMN,
            (long long)LQ * DIMN, 0, (long long)KTP * DIMN);
        cudaEventRecord(eK, s1);
    }

    // --- s2: cached V + V^T projection (single-pass, hi-only out)
    {
        cachev_kernel<<<dim3(KC / 32, DIMN / 32, BATCH), dim3(32, 8), 0, s2>>>(cached_v);
        gemm_mma<1,2,0,0><<<dim3(LQ / BNT, DIMN / BMT, BATCH), 256, SMEM_MMA, s2>>>(
            wvh, ch, ch, bv, nullptr, vh + KC, nullptr,
            DIMN, DIMN, DIMN, KT,
            0, (long long)LQ * DIMN, (long long)DIMN * KT);
        cudaEventRecord(eV, s2);
    }

    // --- s0: Q projection (2-pass)
    gemm_mma<1,1,0,1><<<dim3(DIMN / BNT, (BATCH * LQ) / BMT, 1), 256, SMEM_MMA>>>(
        ch, wqh, wql, bq, nullptr, qh, nullptr,
        DIMN, DIMN, DIMN, DIMN, 0, 0, 0);

    // join K, then S = Q @ K^T (2-pass)
    cudaStreamWaitEvent(0, eK, 0);
    gemm_mma<0,0,1,1><<<dim3(KTP / BNT, LQ / BMT, BATCH), 256, SMEM_MMA>>>(
        qh, kh, kl, nullptr, s, nullptr, nullptr,
        DIMN, DIMN, DIMN, KTP,
        (long long)LQ * DIMN, (long long)KTP * DIMN, (long long)LQ * KTP);

    // masked softmax -> fp16 weights
    softmax_kernel<<<dim3(LQ, BATCH), 256>>>(s, phh, scale);

    // join V, then attended = P @ V (single-pass, K loop clamped, heavy rows first)
    cudaStreamWaitEvent(0, eV, 0);
    gemm_mma<1,0,2,0><<<dim3(DIMN / BNT, LQ / BMT, BATCH), 256, SMEM_MMA>>>(
        phh, vh, vh, nullptr, nullptr, ahh, nullptr,
        KT, KT, KT, DIMN,
        (long long)LQ * KT, (long long)DIMN * KT, (long long)LQ * DIMN);

    // output projection: attended(hi) @ Wo(hi)^T + bo -> fp32 out (single-pass)
    gemm_mma<0,1,0,0><<<dim3(DIMN / BNT, (BATCH * LQ) / BMT, 1), 256, SMEM_MMA>>>(
        ahh, woh, woh, bo, out, nullptr, nullptr,
        DIMN, DIMN, DIMN, DIMN, 0, 0, 0);
}

// round 12
// speedup vs baseline: 1.8780x; 1.3386x over previous
#include <cuda_runtime.h>
#include <cuda_fp16.h>
#include <math.h>
#include <stdint.h>

#define DIMN 2048
#define BATCH 4
#define LQ    4096
#define KC    576
#define KT    4672          // KC + LQ
#define KTP   4864          // padded N for the S GEMM (38*128)

typedef __half h16;

// ---------------------------------------------------------------------------
// Scratch (__device__ globals — zero-initialized; K rows [KT,KTP) stay 0)
// Fully single-pass fp16 scheme: every operand hi-only, fp32 accumulate.
// Calibrated error model: each hi-only rounding adds ~2.8e-4 in quadrature;
// predicted total ~7.5e-4 < 1e-3.
// ---------------------------------------------------------------------------
__device__ h16 g_ch [(size_t)BATCH*LQ*DIMN];   // chunk hi
__device__ h16 g_wqh[(size_t)DIMN*DIMN];
__device__ h16 g_wkh[(size_t)DIMN*DIMN];
__device__ h16 g_wvh[(size_t)DIMN*DIMN];
__device__ h16 g_woh[(size_t)DIMN*DIMN];
__device__ h16 g_qh [(size_t)BATCH*LQ*DIMN];
__device__ h16 g_kh [(size_t)BATCH*KTP*DIMN];
__device__ h16 g_vh [(size_t)BATCH*DIMN*KT];   // V^T [b][d][kt]
__device__ float g_s [(size_t)BATCH*LQ*KTP];
__device__ h16 g_ph [(size_t)BATCH*LQ*KT];
__device__ h16 g_ah [(size_t)BATCH*LQ*DIMN];

// ---------------------------------------------------------------------------
// helpers
// ---------------------------------------------------------------------------
__device__ __forceinline__ uint32_t s2u(const void* p) {
    uint32_t a;
    asm("{ .reg .u64 t; cvta.to.shared.u64 t, %1; cvt.u32.u64 %0, t; }" : "=r"(a) : "l"(p));
    return a;
}
__device__ __forceinline__ void cpa16(uint32_t d, const void* s) {
    asm volatile("cp.async.cg.shared.global [%0], [%1], 16;" :: "r"(d), "l"(s));
}
#define CP_COMMIT() asm volatile("cp.async.commit_group;" ::: "memory")
#define CP_WAIT1()  asm volatile("cp.async.wait_group 1;" ::: "memory")
#define CP_WAIT0()  asm volatile("cp.async.wait_group 0;" ::: "memory")

#define LDSM4(r, a) \
    asm volatile("ldmatrix.sync.aligned.m8n8.x4.shared.b16 {%0,%1,%2,%3}, [%4];" \
                 : "=r"((r)[0]), "=r"((r)[1]), "=r"((r)[2]), "=r"((r)[3]) : "r"(a))

__device__ __forceinline__ void mma16816(float* d, const uint32_t* a,
                                         uint32_t b0, uint32_t b1) {
    asm volatile(
        "mma.sync.aligned.m16n8k16.row.col.f32.f16.f16.f32 "
        "{%0,%1,%2,%3}, {%4,%5,%6,%7}, {%8,%9}, {%0,%1,%2,%3};"
        : "+f"(d[0]), "+f"(d[1]), "+f"(d[2]), "+f"(d[3])
        : "r"(a[0]), "r"(a[1]), "r"(a[2]), "r"(a[3]), "r"(b0), "r"(b1));
}

__device__ __forceinline__ uint32_t round2h(float x0, float x1) {
    __half2 hp = __floats2half2_rn(x0, x1);
    return *reinterpret_cast<uint32_t*>(&hp);
}

// ---------------------------------------------------------------------------
// fp16 single-pass mma.sync GEMM: C tile 128x128, BK=32, 3-stage cp.async
// pipeline, ONE __syncthreads per k-chunk. C = A·B^T, fp32 accum.
// A[M,K], B[N,K] row-major (NT).
// OUTM: 0 fp32 out, 1 fp16 out.
// BIASM: 0 none, 1 bias[col], 2 bias[row]
// TRI:  0 none, 1 = skip block if col0 >= KC+row0+BMT or col0 >= KT (S GEMM),
//       2 = clamp K loop to KC+row0+BMT (AV GEMM; heavy rows scheduled first)
// ---------------------------------------------------------------------------
#define BMT 128
#define BNT 128
#define BKT 32
#define APAD 40                          // fp16 row stride (32+8) -> 80B
#define TILE_B (128 * APAD * 2)          // 10240 bytes per tile
#define STAGE_B (2 * TILE_B)             // A|B = 20480
#define SMEM_MMA (3 * STAGE_B)           // 61440 bytes (3 stages)

template<int OUTM, int BIASM, int TRI>
__global__ __launch_bounds__(256, 2)
void gemm_mma(const h16* __restrict__ Ah,
              const h16* __restrict__ Bh,
              const float* __restrict__ bias,
              float* __restrict__ Cf, h16* __restrict__ Ch,
              int K, int lda, int ldb, int ldc,
              long long sA, long long sB, long long sC)
{
    // TRI==2: reverse row order so the heaviest (longest-K) CTAs start first
    const int row0 = (TRI == 2 ? (int)(gridDim.y - 1 - blockIdx.y) : (int)blockIdx.y) * BMT;
    const int col0 = blockIdx.x * BNT;
    if (TRI == 1 && (col0 >= KC + row0 + BMT || col0 >= KT)) return; // masked / pad tile

    extern __shared__ h16 sm[];
    const uint32_t smb = s2u(sm);
    const int tid  = threadIdx.x;
    const int lane = tid & 31, warp = tid >> 5;
    const int wm = warp & 1, wn = warp >> 1;    // warp grid 2 (M) x 4 (N)
    const size_t zA = (size_t)blockIdx.z * sA;
    const size_t zB = (size_t)blockIdx.z * sB;
    const size_t zC = (size_t)blockIdx.z * sC;

    int kchunks = K / BKT;
    if (TRI == 2) {
        int lim = (KC + row0 + BMT) / BKT;      // multiple of 32 by construction
        if (lim < kchunks) kchunks = lim;
    }

    // cp.async mapping: rows (tid>>2) and (tid>>2)+64, 16B chunk (tid&3)*8
    const int lrow = tid >> 2;
    const int lcol = (tid & 3) * 8;
    const uint32_t o1 = (lrow * APAD + lcol) * 2;
    const uint32_t o2 = ((lrow + 64) * APAD + lcol) * 2;

    auto issue = [&](int kc, int st) {
        const size_t ao = zA + (size_t)(row0 + lrow) * lda + (size_t)kc * BKT + lcol;
        const size_t bo = zB + (size_t)(col0 + lrow) * ldb + (size_t)kc * BKT + lcol;
        const uint32_t base = smb + st * STAGE_B;
        cpa16(base + o1,          Ah + ao);
        cpa16(base + o2,          Ah + ao + (size_t)64 * lda);
        cpa16(base + TILE_B + o1, Bh + bo);
        cpa16(base + TILE_B + o2, Bh + bo + (size_t)64 * ldb);
    };

    float acc[4][4][4];
#pragma unroll
    for (int i = 0; i < 4; i++)
#pragma unroll
        for (int j = 0; j < 4; j++)
#pragma unroll
            for (int e = 0; e < 4; e++) acc[i][j][e] = 0.f;

    // ldmatrix per-thread address components
    const int am = wm * 64 + (lane & 15);
    const int ak = (lane >> 4) * 8;
    const int bn = wn * 32 + (lane & 15);

    // prologue: fill 2 of the 3 stages
    issue(0, 0); CP_COMMIT();
    if (kchunks > 1) { issue(1, 1); CP_COMMIT(); }

    int st = 0;
    for (int kc = 0; kc < kchunks; ++kc) {
        // ensure group kc is complete
        if (kc + 1 < kchunks) CP_WAIT1(); else CP_WAIT0();
        __syncthreads();   // also covers the WAR hazard for stage (kc+2)%3

        // prefetch chunk kc+2 into the stage consumed at iteration kc-1
        if (kc + 2 < kchunks) {
            int st2 = st + 2; if (st2 >= 3) st2 -= 3;
            issue(kc + 2, st2);
            CP_COMMIT();
        }

        const uint32_t ah_ = smb + st * STAGE_B;
        const uint32_t bh_ = ah_ + TILE_B;
#pragma unroll
        for (int ks = 0; ks < 2; ks++) {
            uint32_t af[4][4], bh[2][4];
#pragma unroll
            for (int mt = 0; mt < 4; mt++)
                LDSM4(af[mt], ah_ + (((am + mt * 16) * APAD) + ks * 16 + ak) * 2);
#pragma unroll
            for (int pr = 0; pr < 2; pr++)
                LDSM4(bh[pr], bh_ + (((bn + pr * 16) * APAD) + ks * 16 + ak) * 2);
#pragma unroll
            for (int mt = 0; mt < 4; mt++)
#pragma unroll
                for (int nt = 0; nt < 4; nt++)
                    mma16816(acc[mt][nt], af[mt],
                             bh[nt >> 1][nt & 1], bh[nt >> 1][(nt & 1) + 2]);
        }
        if (++st == 3) st = 0;
    }

    // epilogue
    const int crow = lane >> 2;
    const int ccol = (lane & 3) * 2;
#pragma unroll
    for (int mt = 0; mt < 4; mt++) {
        const size_t r0g = (size_t)row0 + wm * 64 + mt * 16 + crow;
#pragma unroll
        for (int nt = 0; nt < 4; nt++) {
            const int cg = col0 + wn * 32 + nt * 8 + ccol;
            float v0 = acc[mt][nt][0], v1 = acc[mt][nt][1];
            float v2 = acc[mt][nt][2], v3 = acc[mt][nt][3];
            if (BIASM == 1) {
                const float b0 = bias[cg], b1 = bias[cg + 1];
                v0 += b0; v1 += b1; v2 += b0; v3 += b1;
            }
            if (BIASM == 2) {
                const float b0 = bias[r0g], b1 = bias[r0g + 8];
                v0 += b0; v1 += b0; v2 += b1; v3 += b1;
            }
            if (OUTM == 0) {
                *reinterpret_cast<float2*>(&Cf[zC + r0g * ldc + cg])       = make_float2(v0, v1);
                *reinterpret_cast<float2*>(&Cf[zC + (r0g + 8) * ldc + cg]) = make_float2(v2, v3);
            } else {
                *reinterpret_cast<uint32_t*>(&Ch[zC + r0g * ldc + cg])       = round2h(v0, v1);
                *reinterpret_cast<uint32_t*>(&Ch[zC + (r0g + 8) * ldc + cg]) = round2h(v2, v3);
            }
        }
    }
}

// ---------------------------------------------------------------------------
// Elementwise fp32 -> fp16
// ---------------------------------------------------------------------------
__global__ void round_kernel(const float* __restrict__ src, h16* __restrict__ h, size_t n4)
{
    size_t i = (size_t)blockIdx.x * blockDim.x + threadIdx.x;
    if (i >= n4) return;
    float4 v = reinterpret_cast<const float4*>(src)[i];
    reinterpret_cast<uint2*>(h)[i] = make_uint2(round2h(v.x, v.y), round2h(v.z, v.w));
}

// cached_k [B,KC,D] -> fp16 into front rows of g_kh (row stride KTP per batch)
__global__ void cachek_kernel(const float* __restrict__ ck)
{
    const size_t per = (size_t)KC * DIMN / 4;
    size_t i = (size_t)blockIdx.x * blockDim.x + threadIdx.x;
    if (i >= BATCH * per) return;
    size_t b = i / per, r = i - b * per;
    float4 v = reinterpret_cast<const float4*>(ck)[i];
    size_t dst = b * ((size_t)KTP * DIMN / 4) + r;
    reinterpret_cast<uint2*>(g_kh)[dst] = make_uint2(round2h(v.x, v.y), round2h(v.z, v.w));
}

// cached_v [B,KC,D] -> transposed (hi only) into g_vh [B,D,KT] cols [0,KC)
__global__ void cachev_kernel(const float* __restrict__ cv)
{
    __shared__ float t[32][33];
    const int b = blockIdx.z;
    const int r0 = blockIdx.x * 32;   // kc
    const int c0 = blockIdx.y * 32;   // d
    const int tx = threadIdx.x, ty0 = threadIdx.y;
#pragma unroll
    for (int s = 0; s < 4; s++) {
        int ty = ty0 + s * 8;
        t[ty][tx] = cv[((size_t)b * KC + r0 + ty) * DIMN + c0 + tx];
    }
    __syncthreads();
#pragma unroll
    for (int s = 0; s < 4; s++) {
        int ty = ty0 + s * 8;
        size_t o = ((size_t)b * DIMN + c0 + ty) * KT + r0 + tx;
        g_vh[o] = __float2half_rn(t[tx][ty]);
    }
}

// ---------------------------------------------------------------------------
// Masked softmax: row q sees [0, KC+q+1); emits fp16 weights (0 beyond).
// ---------------------------------------------------------------------------
__global__ void softmax_kernel(const float* __restrict__ S, h16* __restrict__ Wh,
                               float scale)
{
    __shared__ float sbuf[KT];
    __shared__ float red[256];
    const int q = blockIdx.x, b = blockIdx.y;
    const float* row = S + ((size_t)b * LQ + q) * KTP;
    h16* wh = Wh + ((size_t)b * LQ + q) * KT;
    const int valid = KC + q + 1;
    const int tid = threadIdx.x;

    float m = -1e30f;
    for (int c = tid; c < valid; c += 256) m = fmaxf(m, row[c] * scale);
    red[tid] = m; __syncthreads();
    for (int s = 128; s > 0; s >>= 1) { if (tid < s) red[tid] = fmaxf(red[tid], red[tid + s]); __syncthreads(); }
    m = red[0]; __syncthreads();

    float sum = 0.f;
    for (int c = tid; c < valid; c += 256) {
        float e = __expf(row[c] * scale - m);
        sbuf[c] = e;
        sum += e;
    }
    red[tid] = sum; __syncthreads();
    for (int s = 128; s > 0; s >>= 1) { if (tid < s) red[tid] += red[tid + s]; __syncthreads(); }
    const float inv = 1.f / red[0];
    __syncthreads();

    for (int c = tid; c < KT; c += 256)
        wh[c] = __float2half_rn((c < valid) ? sbuf[c] * inv : 0.f);
}

// ---------------------------------------------------------------------------
// kernel_launch — graph captured with event-forked streams:
//   s0(default): conversions -> Q proj -> (wait K) S -> softmax -> (wait V) AV -> O
//   s1: cachek + K proj        s2: cachev + V^T proj (overlaps S/softmax)
// ---------------------------------------------------------------------------
extern "C" void kernel_launch(void* const* d_in, const int* in_sizes, int n_in,
                              void* d_out, int out_size)
{
    const float* chunk    = (const float*)d_in[0];
    const float* cached_k = (const float*)d_in[1];
    const float* cached_v = (const float*)d_in[2];
    int wi = 3;
    while (wi < n_in && in_sizes[wi] != DIMN * DIMN) wi++;
    const float* Wq = (const float*)d_in[wi + 0];
    const float* bq = (const float*)d_in[wi + 1];
    const float* Wk = (const float*)d_in[wi + 2];
    const float* bk = (const float*)d_in[wi + 3];
    const float* Wv = (const float*)d_in[wi + 4];
    const float* bv = (const float*)d_in[wi + 5];
    const float* Wo = (const float*)d_in[wi + 6];
    const float* bo = (const float*)d_in[wi + 7];
    float* out = (float*)d_out;

    h16 *ch, *wqh, *wkh, *wvh, *woh, *qh, *kh, *vh, *phh, *ahh;
    float* s;
    cudaGetSymbolAddress((void**)&ch, g_ch);
    cudaGetSymbolAddress((void**)&wqh, g_wqh);
    cudaGetSymbolAddress((void**)&wkh, g_wkh);
    cudaGetSymbolAddress((void**)&wvh, g_wvh);
    cudaGetSymbolAddress((void**)&woh, g_woh);
    cudaGetSymbolAddress((void**)&qh, g_qh);
    cudaGetSymbolAddress((void**)&kh, g_kh);
    cudaGetSymbolAddress((void**)&vh, g_vh);
    cudaGetSymbolAddress((void**)&s, g_s);
    cudaGetSymbolAddress((void**)&phh, g_ph);
    cudaGetSymbolAddress((void**)&ahh, g_ah);

    cudaFuncSetAttribute(gemm_mma<1,1,0>, cudaFuncAttributeMaxDynamicSharedMemorySize, SMEM_MMA);
    cudaFuncSetAttribute(gemm_mma<1,2,0>, cudaFuncAttributeMaxDynamicSharedMemorySize, SMEM_MMA);
    cudaFuncSetAttribute(gemm_mma<0,0,1>, cudaFuncAttributeMaxDynamicSharedMemorySize, SMEM_MMA);
    cudaFuncSetAttribute(gemm_mma<1,0,2>, cudaFuncAttributeMaxDynamicSharedMemorySize, SMEM_MMA);
    cudaFuncSetAttribute(gemm_mma<0,1,0>, cudaFuncAttributeMaxDynamicSharedMemorySize, SMEM_MMA);

    // one-time host-side handles (no device memory involved)
    static cudaStream_t s1 = nullptr, s2 = nullptr;
    static cudaEvent_t e0 = nullptr, eK = nullptr, eV = nullptr;
    if (s1 == nullptr) {
        cudaStreamCreateWithFlags(&s1, cudaStreamNonBlocking);
        cudaStreamCreateWithFlags(&s2, cudaStreamNonBlocking);
        cudaEventCreateWithFlags(&e0, cudaEventDisableTiming);
        cudaEventCreateWithFlags(&eK, cudaEventDisableTiming);
        cudaEventCreateWithFlags(&eV, cudaEventDisableTiming);
    }

    const float scale = (float)(1.0 / sqrt((double)DIMN));

    // --- conversions on the capture (default) stream
    {
        size_t n4 = (size_t)BATCH * LQ * DIMN / 4;
        round_kernel<<<(unsigned)((n4 + 255) / 256), 256>>>(chunk, ch, n4);
        size_t w4 = (size_t)DIMN * DIMN / 4;
        unsigned wg = (unsigned)((w4 + 255) / 256);
        round_kernel<<<wg, 256>>>(Wq, wqh, w4);
        round_kernel<<<wg, 256>>>(Wk, wkh, w4);
        round_kernel<<<wg, 256>>>(Wv, wvh, w4);
        round_kernel<<<wg, 256>>>(Wo, woh, w4);
    }
    cudaEventRecord(e0, 0);
    cudaStreamWaitEvent(s1, e0, 0);
    cudaStreamWaitEvent(s2, e0, 0);

    // --- s1: cached K + K projection
    {
        size_t ck4 = (size_t)BATCH * KC * DIMN / 4;
        cachek_kernel<<<(unsigned)((ck4 + 255) / 256), 256, 0, s1>>>(cached_k);
        gemm_mma<1,1,0><<<dim3(DIMN / BNT, LQ / BMT, BATCH), 256, SMEM_MMA, s1>>>(
            ch, wkh, bk, nullptr, kh + (size_t)KC * DIMN,
            DIMN, DIMN, DIMN, DIMN,
            (long long)LQ * DIMN, 0, (long long)KTP * DIMN);
        cudaEventRecord(eK, s1);
    }

    // --- s2: cached V + V^T projection
    {
        cachev_kernel<<<dim3(KC / 32, DIMN / 32, BATCH), dim3(32, 8), 0, s2>>>(cached_v);
        gemm_mma<1,2,0><<<dim3(LQ / BNT, DIMN / BMT, BATCH), 256, SMEM_MMA, s2>>>(
            wvh, ch, bv, nullptr, vh + KC,
            DIMN, DIMN, DIMN, KT,
            0, (long long)LQ * DIMN, (long long)DIMN * KT);
        cudaEventRecord(eV, s2);
    }

    // --- s0: Q projection
    gemm_mma<1,1,0><<<dim3(DIMN / BNT, (BATCH * LQ) / BMT, 1), 256, SMEM_MMA>>>(
        ch, wqh, bq, nullptr, qh,
        DIMN, DIMN, DIMN, DIMN, 0, 0, 0);

    // join K, then S = Q @ K^T (masked + pad tiles skipped)
    cudaStreamWaitEvent(0, eK, 0);
    gemm_mma<0,0,1><<<dim3(KTP / BNT, LQ / BMT, BATCH), 256, SMEM_MMA>>>(
        qh, kh, nullptr, s, nullptr,
        DIMN, DIMN, DIMN, KTP,
        (long long)LQ * DIMN, (long long)KTP * DIMN, (long long)LQ * KTP);

    // masked softmax -> fp16 weights
    softmax_kernel<<<dim3(LQ, BATCH), 256>>>(s, phh, scale);

    // join V, then attended = P @ V (K loop clamped, heavy rows first)
    cudaStreamWaitEvent(0, eV, 0);
    gemm_mma<1,0,2><<<dim3(DIMN / BNT, LQ / BMT, BATCH), 256, SMEM_MMA>>>(
        phh, vh, nullptr, nullptr, ahh,
        KT, KT, KT, DIMN,
        (long long)LQ * KT, (long long)DIMN * KT, (long long)LQ * DIMN);

    // output projection: attended @ Wo^T + bo -> fp32 out
    gemm_mma<0,1,0><<<dim3(DIMN / BNT, (BATCH * LQ) / BMT, 1), 256, SMEM_MMA>>>(
        ahh, woh, bo, out, nullptr,
        DIMN, DIMN, DIMN, DIMN, 0, 0, 0);
}